// round 12
// baseline (speedup 1.0000x reference)
#include <cuda_runtime.h>
#include <cuda_bf16.h>
#include <math.h>
#include <stdint.h>

// ---------------- problem constants ----------------
#define NN   40000
#define EE   128000
#define E2C  16000
#define EPGC 32000
#define BC   4
#define ML   128
#define ZETA 1e-6f
#define PEXP 1.852f
#define INVP (1.0f/1.852f)
#define I_LAYERS 3
#define K_ITERS  4
#define J_HEADS  6

#define SELU_SCALE 1.0507009873554805f
#define SELU_ALPHA 1.6732632423543772f
#define ENC_NEGINF 0x007FFFFFu

#define AST 136
#define SM_ALO_OFF (128*AST)
#define SM_TOT (2*128*AST*2)   // 69632 bytes

// ---------------- device scratch ----------------
__device__ unsigned agg_buf[NN*ML];
__device__ float    u_buf[NN*ML];
__device__ float    v_buf[NN*ML];
__device__ float    w_buf[(size_t)EE*ML];
__device__ unsigned short ghi_buf[NN*ML],  glo_buf[NN*ML];
__device__ unsigned short zhi_buf[(size_t)EE*ML], zlo_buf[(size_t)EE*ML];
__device__ unsigned short thi_buf[NN*ML],  tlo_buf[NN*ML];
__device__ float    qh_buf[EE];
__device__ float    qt_buf[EE];
__device__ float    hl_buf[EE];
__device__ float    dh_buf[NN];
__device__ float    hA_buf[NN];
__device__ float    hB_buf[NN];
__device__ unsigned short wpk_buf[(size_t)25*32768];
// CSR of incoming edges per node (by rcvr)
__device__ int csr_off[NN+1];
__device__ int csr_pos[NN];
__device__ int csr_e[EE];

// ---------------- scalar helpers ----------------
__device__ __forceinline__ float selu_f(float x){
    return x > 0.f ? SELU_SCALE * x : SELU_SCALE * SELU_ALPHA * (__expf(x) - 1.f);
}
__device__ __forceinline__ unsigned fenc(float f){
    unsigned u = __float_as_uint(f);
    return (u >> 31) ? ~u : (u | 0x80000000u);
}
__device__ __forceinline__ float fdec(unsigned u){
    return (u >> 31) ? __uint_as_float(u & 0x7fffffffu) : __uint_as_float(~u);
}
__device__ __forceinline__ float signf(float x){
    return (x > 0.f) ? 1.f : ((x < 0.f) ? -1.f : 0.f);
}
__device__ __forceinline__ void mma16816(float* d, const unsigned* a, unsigned b0, unsigned b1){
    asm volatile("mma.sync.aligned.m16n8k16.row.col.f32.bf16.bf16.f32 "
        "{%0,%1,%2,%3}, {%4,%5,%6,%7}, {%8,%9}, {%0,%1,%2,%3};"
        : "+f"(d[0]), "+f"(d[1]), "+f"(d[2]), "+f"(d[3])
        : "r"(a[0]), "r"(a[1]), "r"(a[2]), "r"(a[3]), "r"(b0), "r"(b1));
}
__device__ __forceinline__ void ldsm_x4(unsigned* r, uint32_t addr){
    asm volatile("ldmatrix.sync.aligned.m8n8.x4.shared.b16 {%0,%1,%2,%3}, [%4];"
        : "=r"(r[0]), "=r"(r[1]), "=r"(r[2]), "=r"(r[3]) : "r"(addr));
}
__device__ __forceinline__ uint32_t smem_u32(const void* p){
    uint32_t a;
    asm("{ .reg .u64 t; cvta.to.shared.u64 t, %1; cvt.u32.u64 %0, t; }" : "=r"(a) : "l"(p));
    return a;
}
__device__ __forceinline__ void cp_async16(uint32_t dst, const void* src){
    asm volatile("cp.async.ca.shared.global [%0], [%1], 16;" :: "r"(dst), "l"(src));
}
__device__ __forceinline__ void cp_async_wait_all(){
    asm volatile("cp.async.commit_group;\n\tcp.async.wait_group 0;" ::: "memory");
}
__device__ __forceinline__ void ld16(const float* p, float* v){
    #pragma unroll
    for (int i = 0; i < 4; i++){
        float4 t = *(const float4*)(p + 4*i);
        v[4*i]=t.x; v[4*i+1]=t.y; v[4*i+2]=t.z; v[4*i+3]=t.w;
    }
}
__device__ __forceinline__ void split_pack(const float* vals, unsigned* hi2, unsigned* lo2){
    #pragma unroll
    for (int j = 0; j < 8; j++){
        float a = vals[2*j], b = vals[2*j+1];
        __nv_bfloat16 ha = __float2bfloat16_rn(a);
        __nv_bfloat16 hb = __float2bfloat16_rn(b);
        float ra = a - __bfloat162float(ha);
        float rb = b - __bfloat162float(hb);
        __nv_bfloat162 hp = __halves2bfloat162(ha, hb);
        __nv_bfloat162 lp = __halves2bfloat162(__float2bfloat16_rn(ra), __float2bfloat16_rn(rb));
        hi2[j] = *reinterpret_cast<unsigned*>(&hp);
        lo2[j] = *reinterpret_cast<unsigned*>(&lp);
    }
}
__device__ __forceinline__ void split1(float a, unsigned short& h, unsigned short& l){
    __nv_bfloat16 hb = __float2bfloat16_rn(a);
    float rr = a - __bfloat162float(hb);
    __nv_bfloat16 lb = __float2bfloat16_rn(rr);
    h = *reinterpret_cast<unsigned short*>(&hb);
    l = *reinterpret_cast<unsigned short*>(&lb);
}

// ---------------- weight prep: single launch, 25 chunks ----------------
__global__ void k_prep(const float* We1, const float* We2, const float* Wn1,
                       const float* Wn2, const float* Wf1, const float* Wf2){
    int c = blockIdx.x;
    const float* src;
    if      (c < 9)  src = We1 + (size_t)(c/3)*384*ML + (size_t)(c%3)*128*128;
    else if (c < 12) src = We2 + (size_t)(c-9)*ML*ML;
    else if (c < 18) src = Wn1 + (size_t)((c-12)/2)*256*ML + (size_t)((c-12)%2)*128*128;
    else if (c < 21) src = Wn2 + (size_t)(c-18)*ML*ML;
    else if (c < 24) src = Wf1 + (size_t)(c-21)*128*128;
    else             src = Wf2;
    unsigned short* dp = wpk_buf + (size_t)c*32768;
    for (int idx = threadIdx.x; idx < 16384; idx += blockDim.x){
        int k = idx >> 7, n = idx & 127;
        float vv = src[(size_t)k*128 + n];
        __nv_bfloat16 h = __float2bfloat16_rn(vv);
        float rr = vv - __bfloat162float(h);
        __nv_bfloat16 l = __float2bfloat16_rn(rr);
        int kc = k >> 4, kk = k & 15;
        int r = kk >> 3, q = (kk >> 1) & 3, hh = kk & 1;
        int nt = n >> 3, lane = ((n & 7) << 2) + q;
        size_t base = ((size_t)((kc*16 + nt)*32 + lane))*8;
        dp[base + r*2 + hh]     = *reinterpret_cast<unsigned short*>(&h);
        dp[base + 4 + r*2 + hh] = *reinterpret_cast<unsigned short*>(&l);
    }
}

// ---------------- CSR build ----------------
__global__ void k_csr_zero(){
    int n = blockIdx.x*blockDim.x + threadIdx.x;
    if (n < NN) csr_pos[n] = 0;
}
__global__ void k_csr_deg(const int* __restrict__ rc){
    int e = blockIdx.x*blockDim.x + threadIdx.x;
    if (e < EE) atomicAdd(&csr_pos[rc[e]], 1);
}
// single-block scan: 1024 threads, each handles ceil(NN/1024) nodes
__global__ void k_csr_scan(){
    __shared__ int part[1024];
    const int T = 1024, C = (NN + T - 1) / T;   // 40
    int t = threadIdx.x;
    int s = 0;
    for (int i = 0; i < C; i++){
        int n = t*C + i;
        if (n < NN) s += csr_pos[n];
    }
    part[t] = s;
    __syncthreads();
    // inclusive scan of partials (simple Hillis-Steele)
    for (int o = 1; o < T; o <<= 1){
        int x = (t >= o) ? part[t-o] : 0;
        __syncthreads();
        part[t] += x;
        __syncthreads();
    }
    int run = (t == 0) ? 0 : part[t-1];
    for (int i = 0; i < C; i++){
        int n = t*C + i;
        if (n < NN){
            int d = csr_pos[n];
            csr_off[n] = run;
            csr_pos[n] = run;
            run += d;
        }
    }
    if (t == T-1) csr_off[NN] = EE;
}
__global__ void k_csr_fill(const int* __restrict__ rc){
    int e = blockIdx.x*blockDim.x + threadIdx.x;
    if (e >= EE) return;
    int p = atomicAdd(&csr_pos[rc[e]], 1);
    csr_e[p] = e;
}

// ================= unified multi-job GEMM (copy or EDGEIN staging) =================
// flags: bit0 = OUTSPLIT, bit1 = HALFE row map, bit2 = EDGEIN staging
struct CJob {
    const unsigned short *PH, *PL, *B;
    const float *q0, *q1, *Wei;
    float *C;
    unsigned short *SH, *SL;
    int nblocks, M, flags;
};
struct CJobs { CJob j[3]; };

__global__ void __launch_bounds__(256,2) tcg_jobs(CJobs js){
    extern __shared__ unsigned short As[];
    int b = blockIdx.x;
    CJob J;
    if (b < js.j[0].nblocks) J = js.j[0];
    else {
        b -= js.j[0].nblocks;
        if (b < js.j[1].nblocks) J = js.j[1];
        else { b -= js.j[1].nblocks; J = js.j[2]; }
    }
    const int tid = threadIdx.x, wid = tid >> 5, lane = tid & 31;
    const int row0 = (J.flags & 2) ? (b/125)*EPGC + (b%125)*128 : b*128;
    const int mq = wid & 1, nh = wid >> 1;

    const uint32_t sbase = smem_u32(As);
    const uint32_t a_h0 = sbase + ((mq*64 + (lane & 15))*AST + (lane >> 4)*8) * 2;
    const uint32_t a_l0 = a_h0 + SM_ALO_OFF*2;

    if (J.flags & 4){
        // EDGEIN staging: z = selu(selu(q0)*Wei[0,:] + selu(q1)*Wei[1,:])
        #pragma unroll 2
        for (int p = 0; p < 4; p++){
            int m  = p*32 + (tid >> 3);
            int c0 = (tid & 7) * 16;
            int grow = row0 + m; if (grow > J.M-1) grow = J.M-1;
            float sqt = selu_f(J.q0[grow]);
            float sqh = selu_f(J.q1[grow]);
            float w0[16], w1[16], vals[16];
            ld16(J.Wei + c0, w0);
            ld16(J.Wei + ML + c0, w1);
            #pragma unroll
            for (int j = 0; j < 16; j++) vals[j] = selu_f(sqt*w0[j] + sqh*w1[j]);
            unsigned hi2[8], lo2[8];
            split_pack(vals, hi2, lo2);
            unsigned short* dh_ = As + m*AST + c0;
            unsigned short* dl_ = dh_ + SM_ALO_OFF;
            *(uint4*)(dh_)     = make_uint4(hi2[0], hi2[1], hi2[2], hi2[3]);
            *(uint4*)(dh_ + 8) = make_uint4(hi2[4], hi2[5], hi2[6], hi2[7]);
            *(uint4*)(dl_)     = make_uint4(lo2[0], lo2[1], lo2[2], lo2[3]);
            *(uint4*)(dl_ + 8) = make_uint4(lo2[4], lo2[5], lo2[6], lo2[7]);
        }
    } else {
        #pragma unroll
        for (int p = 0; p < 4; p++){
            int m  = p*32 + (tid >> 3);
            int c0 = (tid & 7) * 16;
            int grow = row0 + m; if (grow > J.M-1) grow = J.M-1;
            uint32_t dh_ = sbase + (m*AST + c0)*2;
            uint32_t dl_ = dh_ + SM_ALO_OFF*2;
            const unsigned short* ph = J.PH + (size_t)grow*ML + c0;
            const unsigned short* pl = J.PL + (size_t)grow*ML + c0;
            cp_async16(dh_,      ph);
            cp_async16(dh_ + 16, ph + 8);
            cp_async16(dl_,      pl);
            cp_async16(dl_ + 16, pl + 8);
        }
        cp_async_wait_all();
    }
    __syncthreads();

    float acc[4][4][4];
    #pragma unroll
    for (int i = 0; i < 4; i++)
        #pragma unroll
        for (int j = 0; j < 4; j++)
            #pragma unroll
            for (int t = 0; t < 4; t++) acc[i][j][t] = 0.f;

    const uint4* Bw = (const uint4*)J.B;
    #pragma unroll 1
    for (int kc = 0; kc < 8; kc++){
        uint4 bq[4];
        #pragma unroll
        for (int j = 0; j < 4; j++)
            bq[j] = Bw[(size_t)((kc*16 + nh*4 + j)*32 + lane)];
        #pragma unroll
        for (int i = 0; i < 4; i++){
            unsigned ah[4], al[4];
            ldsm_x4(ah, a_h0 + kc*32 + i*(16*AST*2));
            ldsm_x4(al, a_l0 + kc*32 + i*(16*AST*2));
            #pragma unroll
            for (int j = 0; j < 4; j++){
                mma16816(acc[i][j], ah, bq[j].x, bq[j].y);
                mma16816(acc[i][j], ah, bq[j].z, bq[j].w);
                mma16816(acc[i][j], al, bq[j].x, bq[j].y);
            }
        }
    }

    const int rb = row0 + mq*64 + (lane >> 2);
    const int cb = nh*32 + (lane & 3)*2;
    const bool outsplit = J.flags & 1;
    #pragma unroll
    for (int i = 0; i < 4; i++){
        #pragma unroll
        for (int h = 0; h < 2; h++){
            int row = rb + i*16 + h*8;
            if (row >= J.M) continue;
            if (outsplit){
                #pragma unroll
                for (int j = 0; j < 4; j++){
                    float a0 = selu_f(acc[i][j][2*h]);
                    float a1 = selu_f(acc[i][j][2*h+1]);
                    unsigned short h0,l0,h1,l1;
                    split1(a0, h0, l0); split1(a1, h1, l1);
                    size_t o = (size_t)row*ML + cb + j*8;
                    *(ushort2*)(J.SH + o) = make_ushort2(h0, h1);
                    *(ushort2*)(J.SL + o) = make_ushort2(l0, l1);
                }
            } else {
                float* cp = J.C + (size_t)row*ML + cb;
                #pragma unroll
                for (int j = 0; j < 4; j++)
                    *(float2*)(cp + j*8) = make_float2(acc[i][j][2*h], acc[i][j][2*h+1]);
            }
        }
    }
}

// ================= templated GEMM (EDGEIN / SUM3 / CAT2D) =================
enum { M_SUM3=2, M_CAT2D=3, M_EDGEIN=4 };

template<int NCHUNK, int MODE, bool OUTACT, bool AGGMAX, bool DOTOUT, bool HALFE, bool OUTSPLIT>
__global__ void __launch_bounds__(256,2) tcg(
    const float* __restrict__ A0, const float* __restrict__ A1,
    const float* __restrict__ A2, const unsigned* __restrict__ AU,
    const unsigned short* __restrict__ PH, const unsigned short* __restrict__ PL,
    const int* __restrict__ iS, const int* __restrict__ iR,
    const unsigned short* __restrict__ Bpk,
    float* __restrict__ C,
    unsigned short* __restrict__ SH, unsigned short* __restrict__ SL,
    unsigned* __restrict__ aggU, const int* __restrict__ rcv,
    const float* __restrict__ Wf3, float* __restrict__ qout, int M, int skipz2)
{
    extern __shared__ unsigned short As[];
    const int tid = threadIdx.x, wid = tid >> 5, lane = tid & 31;
    const int row0 = HALFE ? (blockIdx.x/125)*EPGC + (blockIdx.x%125)*128
                           : blockIdx.x*128;
    const int mq = wid & 1, nh = wid >> 1;

    const uint32_t sbase = smem_u32(As);
    const uint32_t a_h0 = sbase + ((mq*64 + (lane & 15))*AST + (lane >> 4)*8) * 2;
    const uint32_t a_l0 = a_h0 + SM_ALO_OFF*2;

    float acc[4][4][4];
    #pragma unroll
    for (int i = 0; i < 4; i++)
        #pragma unroll
        for (int j = 0; j < 4; j++)
            #pragma unroll
            for (int t = 0; t < 4; t++) acc[i][j][t] = 0.f;

    #pragma unroll 1
    for (int ch = 0; ch < NCHUNK; ch++){
        if (MODE == M_CAT2D && ch == 0){
            #pragma unroll
            for (int p = 0; p < 4; p++){
                int m  = p*32 + (tid >> 3);
                int c0 = (tid & 7) * 16;
                int grow = row0 + m; if (grow > M-1) grow = M-1;
                uint32_t dh_ = sbase + (m*AST + c0)*2;
                uint32_t dl_ = dh_ + SM_ALO_OFF*2;
                const unsigned short* ph = PH + (size_t)grow*ML + c0;
                const unsigned short* pl = PL + (size_t)grow*ML + c0;
                cp_async16(dh_,      ph);
                cp_async16(dh_ + 16, ph + 8);
                cp_async16(dl_,      pl);
                cp_async16(dl_ + 16, pl + 8);
            }
            cp_async_wait_all();
        } else {
            #pragma unroll 2
            for (int p = 0; p < 4; p++){
                int m  = p*32 + (tid >> 3);
                int c0 = (tid & 7) * 16;
                int grow = row0 + m;
                bool canon = (grow <= M-1);
                if (!canon) grow = M-1;
                unsigned short* dh_ = As + m*AST + c0;
                unsigned short* dl_ = dh_ + SM_ALO_OFF;
                float vals[16];
                if (MODE == M_SUM3){
                    const float* pa = A0 + (size_t)iS[grow]*ML + c0;
                    const float* pb = A1 + (size_t)iR[grow]*ML + c0;
                    const float* pc = A2 + (size_t)grow*ML + c0;
                    float va[16], vb[16], vc[16];
                    ld16(pa, va); ld16(pb, vb); ld16(pc, vc);
                    #pragma unroll
                    for (int j = 0; j < 16; j++) vals[j] = selu_f(va[j] + vb[j] + vc[j]);
                } else if (MODE == M_EDGEIN){
                    float sqt = selu_f(A0[grow]);
                    float sqh = selu_f(A2[grow]);
                    float w0[16], w1[16];
                    ld16(A1 + c0, w0);
                    ld16(A1 + ML + c0, w1);
                    #pragma unroll
                    for (int j = 0; j < 16; j++) vals[j] = selu_f(sqt*w0[j] + sqh*w1[j]);
                } else { // M_CAT2D ch1
                    const unsigned* pu = AU + (size_t)grow*ML + c0;
                    uint4* pw = (uint4*)const_cast<unsigned*>(pu);
                    #pragma unroll
                    for (int i = 0; i < 4; i++){
                        uint4 t = *(const uint4*)(pu + 4*i);
                        if (canon)
                            pw[i] = make_uint4(ENC_NEGINF,ENC_NEGINF,ENC_NEGINF,ENC_NEGINF);
                        unsigned uu[4] = {t.x, t.y, t.z, t.w};
                        #pragma unroll
                        for (int j = 0; j < 4; j++){
                            float d = (uu[j] == ENC_NEGINF) ? 0.f : fdec(uu[j]);
                            vals[4*i + j] = selu_f(d);
                        }
                    }
                }
                unsigned hi2[8], lo2[8];
                split_pack(vals, hi2, lo2);
                *(uint4*)(dh_)     = make_uint4(hi2[0], hi2[1], hi2[2], hi2[3]);
                *(uint4*)(dh_ + 8) = make_uint4(hi2[4], hi2[5], hi2[6], hi2[7]);
                *(uint4*)(dl_)     = make_uint4(lo2[0], lo2[1], lo2[2], lo2[3]);
                *(uint4*)(dl_ + 8) = make_uint4(lo2[4], lo2[5], lo2[6], lo2[7]);
            }
        }
        __syncthreads();

        const uint4* Bw = (const uint4*)(Bpk + (size_t)ch*32768);
        #pragma unroll 1
        for (int kc = 0; kc < 8; kc++){
            uint4 bq[4];
            #pragma unroll
            for (int j = 0; j < 4; j++)
                bq[j] = Bw[(size_t)((kc*16 + nh*4 + j)*32 + lane)];
            #pragma unroll
            for (int i = 0; i < 4; i++){
                unsigned ah[4], al[4];
                ldsm_x4(ah, a_h0 + kc*32 + i*(16*AST*2));
                ldsm_x4(al, a_l0 + kc*32 + i*(16*AST*2));
                #pragma unroll
                for (int j = 0; j < 4; j++){
                    mma16816(acc[i][j], ah, bq[j].x, bq[j].y);
                    mma16816(acc[i][j], ah, bq[j].z, bq[j].w);
                    mma16816(acc[i][j], al, bq[j].x, bq[j].y);
                }
            }
        }
        __syncthreads();
    }

    const int rb = row0 + mq*64 + (lane >> 2);
    const int cb = nh*32 + (lane & 3)*2;
    #pragma unroll
    for (int i = 0; i < 4; i++){
        #pragma unroll
        for (int h = 0; h < 2; h++){
            int row = rb + i*16 + h*8;
            bool valid = row < M;
            float f[8];
            #pragma unroll
            for (int j = 0; j < 4; j++){
                f[2*j]   = acc[i][j][2*h];
                f[2*j+1] = acc[i][j][2*h+1];
                if (OUTACT){ f[2*j] = selu_f(f[2*j]); f[2*j+1] = selu_f(f[2*j+1]); }
            }
            if (DOTOUT){
                float s = 0.f;
                #pragma unroll
                for (int j = 0; j < 4; j++){
                    float2 wv = *(const float2*)(Wf3 + cb + j*8);
                    s += f[2*j]*wv.x + f[2*j+1]*wv.y;
                }
                s += __shfl_xor_sync(0xffffffffu, s, 1);
                s += __shfl_xor_sync(0xffffffffu, s, 2);
                if ((lane & 3) == 0 && valid) atomicAdd(qout + row, s);
            } else if (valid){
                if (AGGMAX){
                    unsigned* ap = aggU + (size_t)rcv[row]*ML + cb;
                    #pragma unroll
                    for (int j = 0; j < 4; j++){
                        atomicMax(ap + j*8,     fenc(f[2*j]));
                        atomicMax(ap + j*8 + 1, fenc(f[2*j+1]));
                    }
                }
                if (OUTSPLIT){
                    if (skipz2 && (row % EPGC) >= E2C) continue;
                    #pragma unroll
                    for (int j = 0; j < 4; j++){
                        float a0 = OUTACT ? f[2*j]   : selu_f(f[2*j]);
                        float a1 = OUTACT ? f[2*j+1] : selu_f(f[2*j+1]);
                        unsigned short h0,l0,h1,l1;
                        split1(a0, h0, l0); split1(a1, h1, l1);
                        size_t o = (size_t)row*ML + cb + j*8;
                        *(ushort2*)(SH + o) = make_ushort2(h0, h1);
                        *(ushort2*)(SL + o) = make_ushort2(l0, l1);
                    }
                } else if (C){
                    float* cp = C + (size_t)row*ML + cb;
                    #pragma unroll
                    for (int j = 0; j < 4; j++)
                        *(float2*)(cp + j*8) = make_float2(f[2*j], f[2*j+1]);
                }
            }
        }
    }
}

// ---------------- elementwise / segment kernels ----------------
__global__ void k_init(const float* __restrict__ x, float* __restrict__ hA,
                       float* __restrict__ dh, unsigned* __restrict__ agu){
    int i = blockIdx.x*blockDim.x + threadIdx.x;
    if (i < NN*ML) agu[i] = ENC_NEGINF;
    if (i < NN){
        dh[i] = 0.f;
        hA[i] = x[2*i];
    }
}
__global__ void k_copy(const float* __restrict__ a, float* __restrict__ b, int n){
    int i = blockIdx.x*blockDim.x + threadIdx.x;
    if (i < n) b[i] = a[i];
}
__global__ void k_flows(const float* __restrict__ h, const float* __restrict__ r,
                        const int* __restrict__ s, const int* __restrict__ rc,
                        float* __restrict__ q, float* __restrict__ q2){
    int e = blockIdx.x*blockDim.x + threadIdx.x;
    if (e >= EE) return;
    float dh = h[s[e]] - h[rc[e]];
    float qe = signf(dh) * __powf((fabsf(dh) + ZETA) / (r[e] + ZETA), INVP);
    q[e] = qe;
    if (q2) q2[e] = qe;
}
__global__ void k_segsum(const float* __restrict__ q, const int* __restrict__ rc,
                         float* __restrict__ d){
    int e = blockIdx.x*blockDim.x + threadIdx.x;
    if (e < EE) atomicAdd(&d[rc[e]], q[e]);
}
__global__ void k_node_in(const float* __restrict__ dh, const float* __restrict__ x,
                          const float* __restrict__ W,
                          unsigned short* __restrict__ GH, unsigned short* __restrict__ GL){
    int idx = blockIdx.x*blockDim.x + threadIdx.x;
    if (idx >= NN*ML) return;
    int n = idx >> 7, j = idx & 127;
    float gv = selu_f(dh[n]) * W[j] + selu_f(x[2*n+1]) * W[ML + j];
    float sg = selu_f(gv);
    unsigned short h, l;
    split1(sg, h, l);
    GH[idx] = h; GL[idx] = l;
}
// fused: antisym q_hat + hl (edges) + dh=0, hA=h_star (nodes)
__global__ void k_misc(float* __restrict__ qh, const float* __restrict__ r,
                       const float* __restrict__ x,
                       float* __restrict__ hl, float* __restrict__ dh,
                       float* __restrict__ hA){
    int i = blockIdx.x*blockDim.x + threadIdx.x;
    if (i < EE){
        int loc = i % EPGC;
        float qe;
        if (loc >= E2C){ qe = -qh[i - E2C]; qh[i] = qe; }
        else            qe = qh[i];
        float aq = fabsf(qe);
        float p  = (aq < 1e-30f) ? 0.f : __powf(aq, PEXP);
        hl[i] = r[i] * signf(qe) * p;
    }
    if (i < NN){
        dh[i] = 0.f;
        hA[i] = x[2*i];
    }
}
// fused head step via CSR: hnew[n] = res? h* : max(hold[n], max_in(hold[s]-hl))
__global__ void k_head(const float* __restrict__ hold, const float* __restrict__ hl,
                       const int* __restrict__ s, const float* __restrict__ x,
                       float* __restrict__ hnew){
    int n = blockIdx.x*blockDim.x + threadIdx.x;
    if (n >= NN) return;
    float hs = x[2*n];
    if (hs != 0.f){ hnew[n] = hs; return; }
    float m = hold[n];
    int b = csr_off[n], e2 = csr_off[n+1];
    for (int i = b; i < e2; i++){
        int e = csr_e[i];
        m = fmaxf(m, hold[s[e]] - hl[e]);
    }
    hnew[n] = m;
}

// ---------------- host orchestration ----------------
template<typename T>
static T* sym_addr(const void* sym){
    void* p = nullptr;
    cudaGetSymbolAddress(&p, sym);
    return (T*)p;
}
static void set_smem(const void* f){
    cudaFuncSetAttribute(f, cudaFuncAttributeMaxDynamicSharedMemorySize, SM_TOT);
}

extern "C" void kernel_launch(void* const* d_in, const int* in_sizes, int n_in,
                              void* d_out, int out_size)
{
    const float* x    = (const float*)d_in[0];
    const float* r    = (const float*)d_in[1];
    const float* Wni  = (const float*)d_in[2];
    const float* Wei  = (const float*)d_in[3];
    const float* Wf1  = (const float*)d_in[4];
    const float* Wf2  = (const float*)d_in[5];
    const float* Wf3  = (const float*)d_in[6];
    const float* We1  = (const float*)d_in[7];
    const float* We2  = (const float*)d_in[8];
    const float* Wn1  = (const float*)d_in[9];
    const float* Wn2  = (const float*)d_in[10];
    const int*   sndr = (const int*)d_in[11];
    const int*   rcvr = (const int*)d_in[12];
    float*       out  = (float*)d_out;

    unsigned* agu = sym_addr<unsigned>(agg_buf);
    float*    u   = sym_addr<float>(u_buf);
    float*    v   = sym_addr<float>(v_buf);
    float*    w   = sym_addr<float>(w_buf);
    unsigned short* GH = sym_addr<unsigned short>(ghi_buf);
    unsigned short* GL = sym_addr<unsigned short>(glo_buf);
    unsigned short* ZH = sym_addr<unsigned short>(zhi_buf);
    unsigned short* ZL = sym_addr<unsigned short>(zlo_buf);
    unsigned short* TH2= sym_addr<unsigned short>(thi_buf);
    unsigned short* TL2= sym_addr<unsigned short>(tlo_buf);
    float*    qh  = sym_addr<float>(qh_buf);
    float*    qt  = sym_addr<float>(qt_buf);
    float*    hl  = sym_addr<float>(hl_buf);
    float*    dh  = sym_addr<float>(dh_buf);
    float*    hA  = sym_addr<float>(hA_buf);
    float*    hB  = sym_addr<float>(hB_buf);
    unsigned short* WP = sym_addr<unsigned short>(wpk_buf);

    set_smem((const void*)tcg<1,M_EDGEIN,false,false,false,false,false>);
    set_smem((const void*)tcg<1,M_SUM3  ,false,true ,false,false,true >);
    set_smem((const void*)tcg<2,M_CAT2D ,true ,false,false,false,true >);
    set_smem((const void*)tcg<1,M_SUM3  ,true ,false,true ,true ,false>);
    set_smem((const void*)tcg_jobs);

    const int T = 256;
    const int gN  = (NN + T - 1) / T;
    const int gE  = (EE + T - 1) / T;
    const int gNM = (NN*ML + T - 1) / T;

    const int TE = (EE + 127)/128;   // 1000
    const int TN = (NN + 127)/128;   // 313
    const int THF = 500;

    #define CHK(i) (WP + (size_t)(i)*32768)

    auto mkjob = [&](const unsigned short* PH, const unsigned short* PL,
                     const unsigned short* B, float* C,
                     unsigned short* SH, unsigned short* SL,
                     int nb, int M, int flags) -> CJob {
        CJob j; j.PH=PH; j.PL=PL; j.B=B; j.q0=nullptr; j.q1=nullptr; j.Wei=nullptr;
        j.C=C; j.SH=SH; j.SL=SL; j.nblocks=nb; j.M=M; j.flags=flags; return j;
    };
    auto mkedge = [&](const float* q0, const float* q1, const float* W,
                      const unsigned short* B, float* C, int nb) -> CJob {
        CJob j; j.PH=nullptr; j.PL=nullptr; j.B=B; j.q0=q0; j.q1=q1; j.Wei=W;
        j.C=C; j.SH=nullptr; j.SL=nullptr; j.nblocks=nb; j.M=EE; j.flags=4; return j;
    };
    CJob empty = mkjob(nullptr,nullptr,nullptr,nullptr,nullptr,nullptr,0,0,0);

    // ---- visible launches 0..3 (ncu captures visible idx 3 = EDGEIN) ----
    k_prep<<<25, 256>>>(We1, We2, Wn1, Wn2, Wf1, Wf2);          // 0
    k_init<<<gNM, T>>>(x, hA, dh, agu);                         // 1
    k_flows<<<gE, T>>>(hA, r, sndr, rcvr, qh, qt);              // 2
    tcg<1,M_EDGEIN,false,false,false,false,false><<<TE, 256, SM_TOT>>>(   // 3 PROFILED
        qt, Wei, qh, nullptr, nullptr, nullptr, nullptr, nullptr,
        CHK(2), w, nullptr, nullptr, nullptr, nullptr, nullptr, nullptr, EE, 0);
    k_segsum<<<gE, T>>>(qh, rcvr, dh);
    k_node_in<<<gNM, T>>>(dh, x, Wni, GH, GL);
    // CSR build (once)
    k_csr_zero<<<gN, T>>>();
    k_csr_deg<<<gE, T>>>(rcvr);
    k_csr_scan<<<1, 1024>>>();
    k_csr_fill<<<gE, T>>>(rcvr);

    for (int k = 0; k < K_ITERS; k++){
        if (k > 0){
            k_node_in<<<gNM, T>>>(dh, x, Wni, GH, GL);
            // packed: EDGEIN + u0 + v0
            CJobs js = {{ mkedge(qt, qh, Wei, CHK(2), w, TE),
                          mkjob(GH,GL,CHK(0),u,nullptr,nullptr,TN,NN,0),
                          mkjob(GH,GL,CHK(1),v,nullptr,nullptr,TN,NN,0) }};
            tcg_jobs<<<TE+2*TN, 256, SM_TOT>>>(js);
        } else {
            CJobs js = {{ mkjob(GH,GL,CHK(0),u,nullptr,nullptr,TN,NN,0),
                          mkjob(GH,GL,CHK(1),v,nullptr,nullptr,TN,NN,0),
                          empty }};
            tcg_jobs<<<2*TN, 256, SM_TOT>>>(js);
        }

        for (int i = 0; i < I_LAYERS; i++){
            tcg<1,M_SUM3,false,true,false,false,true><<<TE, 256, SM_TOT>>>(
                u, v, w, nullptr, nullptr, nullptr, sndr, rcvr,
                CHK(9+i), nullptr, ZH, ZL, agu, rcvr, nullptr, nullptr, EE, (i==2)?1:0);
            tcg<2,M_CAT2D,true,false,false,false,true><<<TN, 256, SM_TOT>>>(
                nullptr, nullptr, nullptr, agu, GH, GL, nullptr, nullptr,
                CHK(12+2*i), nullptr, TH2, TL2, nullptr, nullptr, nullptr, nullptr, NN, 0);
            if (i < 2){
                CJobs js = {{ mkjob(TH2,TL2,CHK(18+i),nullptr,GH,GL,TN,NN,1),
                              mkjob(ZH,ZL,CHK((i+1)*3+2),w,nullptr,nullptr,TE,EE,0),
                              empty }};
                tcg_jobs<<<TN+TE, 256, SM_TOT>>>(js);
                CJobs js2 = {{ mkjob(GH,GL,CHK((i+1)*3),u,nullptr,nullptr,TN,NN,0),
                               mkjob(GH,GL,CHK((i+1)*3+1),v,nullptr,nullptr,TN,NN,0),
                               empty }};
                tcg_jobs<<<2*TN, 256, SM_TOT>>>(js2);
            } else {
                CJobs js = {{ mkjob(TH2,TL2,CHK(18+i),nullptr,GH,GL,TN,NN,1),
                              empty, empty }};
                tcg_jobs<<<TN, 256, SM_TOT>>>(js);
            }
        }

        // flow head
        {
            CJobs js = {{ mkjob(GH,GL,CHK(21),u,nullptr,nullptr,TN,NN,0),
                          mkjob(GH,GL,CHK(22),v,nullptr,nullptr,TN,NN,0),
                          mkjob(ZH,ZL,CHK(23),w,nullptr,nullptr,THF,EE,2) }};
            tcg_jobs<<<2*TN+THF, 256, SM_TOT>>>(js);
        }
        tcg<1,M_SUM3,true,false,true,true,false><<<THF, 256, SM_TOT>>>(
            u, v, w, nullptr, nullptr, nullptr, sndr, rcvr,
            CHK(24), nullptr, nullptr, nullptr, nullptr, nullptr, Wf3, qh, EE, 0);

        k_misc<<<gE, T>>>(qh, r, x, hl, dh, hA);
        k_segsum<<<gE, T>>>(qh, rcvr, dh);

        // construct_heads via CSR (6 fused steps)
        float* hc = hA; float* hn = hB;
        for (int j = 0; j < J_HEADS; j++){
            k_head<<<gN, T>>>(hc, hl, sndr, x, hn);
            float* t2 = hc; hc = hn; hn = t2;
        }

        k_flows<<<gE, T>>>(hc, r, sndr, rcvr, qt, nullptr);
    }

    k_copy<<<gN, T>>>(hA, out, NN);
    (void)in_sizes; (void)n_in; (void)out_size;
    #undef CHK
}

// round 13
// speedup vs baseline: 1.0102x; 1.0102x over previous
#include <cuda_runtime.h>
#include <cuda_bf16.h>
#include <math.h>
#include <stdint.h>

// ---------------- problem constants ----------------
#define NN   40000
#define EE   128000
#define E2C  16000
#define EPGC 32000
#define BC   4
#define ML   128
#define ZETA 1e-6f
#define PEXP 1.852f
#define INVP (1.0f/1.852f)
#define I_LAYERS 3
#define K_ITERS  4
#define J_HEADS  6

#define SELU_SCALE 1.0507009873554805f
#define SELU_ALPHA 1.6732632423543772f
#define ENC_NEGINF 0x007FFFFFu

#define AST 136
#define SM_ALO_OFF (128*AST)
#define SM_TOT (2*128*AST*2)   // 69632 bytes

// ---------------- device scratch ----------------
__device__ unsigned agg_buf[NN*ML];
__device__ float    u_buf[NN*ML];
__device__ float    v_buf[NN*ML];
__device__ float    w_buf[(size_t)EE*ML];
__device__ unsigned short ghi_buf[NN*ML],  glo_buf[NN*ML];
__device__ unsigned short zhi_buf[(size_t)EE*ML], zlo_buf[(size_t)EE*ML];
__device__ unsigned short thi_buf[NN*ML],  tlo_buf[NN*ML];
__device__ float    qh_buf[EE];
__device__ float    qt_buf[EE];
__device__ float    hl_buf[EE];
__device__ float    dh_buf[NN];
__device__ float    hA_buf[NN];
__device__ float    hB_buf[NN];
__device__ unsigned aggS_buf[NN];
__device__ unsigned short wpk_buf[(size_t)25*32768];

// ---------------- scalar helpers ----------------
__device__ __forceinline__ float selu_f(float x){
    return x > 0.f ? SELU_SCALE * x : SELU_SCALE * SELU_ALPHA * (__expf(x) - 1.f);
}
__device__ __forceinline__ unsigned fenc(float f){
    unsigned u = __float_as_uint(f);
    return (u >> 31) ? ~u : (u | 0x80000000u);
}
__device__ __forceinline__ float fdec(unsigned u){
    return (u >> 31) ? __uint_as_float(u & 0x7fffffffu) : __uint_as_float(~u);
}
__device__ __forceinline__ float signf(float x){
    return (x > 0.f) ? 1.f : ((x < 0.f) ? -1.f : 0.f);
}
__device__ __forceinline__ void mma16816(float* d, const unsigned* a, unsigned b0, unsigned b1){
    asm volatile("mma.sync.aligned.m16n8k16.row.col.f32.bf16.bf16.f32 "
        "{%0,%1,%2,%3}, {%4,%5,%6,%7}, {%8,%9}, {%0,%1,%2,%3};"
        : "+f"(d[0]), "+f"(d[1]), "+f"(d[2]), "+f"(d[3])
        : "r"(a[0]), "r"(a[1]), "r"(a[2]), "r"(a[3]), "r"(b0), "r"(b1));
}
__device__ __forceinline__ void ldsm_x4(unsigned* r, uint32_t addr){
    asm volatile("ldmatrix.sync.aligned.m8n8.x4.shared.b16 {%0,%1,%2,%3}, [%4];"
        : "=r"(r[0]), "=r"(r[1]), "=r"(r[2]), "=r"(r[3]) : "r"(addr));
}
__device__ __forceinline__ uint32_t smem_u32(const void* p){
    uint32_t a;
    asm("{ .reg .u64 t; cvta.to.shared.u64 t, %1; cvt.u32.u64 %0, t; }" : "=r"(a) : "l"(p));
    return a;
}
__device__ __forceinline__ void cp_async16(uint32_t dst, const void* src){
    asm volatile("cp.async.ca.shared.global [%0], [%1], 16;" :: "r"(dst), "l"(src));
}
__device__ __forceinline__ void cp_async_wait_all(){
    asm volatile("cp.async.commit_group;\n\tcp.async.wait_group 0;" ::: "memory");
}
__device__ __forceinline__ void ld16(const float* p, float* v){
    #pragma unroll
    for (int i = 0; i < 4; i++){
        float4 t = *(const float4*)(p + 4*i);
        v[4*i]=t.x; v[4*i+1]=t.y; v[4*i+2]=t.z; v[4*i+3]=t.w;
    }
}
__device__ __forceinline__ void split_pack(const float* vals, unsigned* hi2, unsigned* lo2){
    #pragma unroll
    for (int j = 0; j < 8; j++){
        float a = vals[2*j], b = vals[2*j+1];
        __nv_bfloat16 ha = __float2bfloat16_rn(a);
        __nv_bfloat16 hb = __float2bfloat16_rn(b);
        float ra = a - __bfloat162float(ha);
        float rb = b - __bfloat162float(hb);
        __nv_bfloat162 hp = __halves2bfloat162(ha, hb);
        __nv_bfloat162 lp = __halves2bfloat162(__float2bfloat16_rn(ra), __float2bfloat16_rn(rb));
        hi2[j] = *reinterpret_cast<unsigned*>(&hp);
        lo2[j] = *reinterpret_cast<unsigned*>(&lp);
    }
}
__device__ __forceinline__ void split1(float a, unsigned short& h, unsigned short& l){
    __nv_bfloat16 hb = __float2bfloat16_rn(a);
    float rr = a - __bfloat162float(hb);
    __nv_bfloat16 lb = __float2bfloat16_rn(rr);
    h = *reinterpret_cast<unsigned short*>(&hb);
    l = *reinterpret_cast<unsigned short*>(&lb);
}

// ---------------- weight prep ----------------
__global__ void k_prep(const float* We1, const float* We2, const float* Wn1,
                       const float* Wn2, const float* Wf1, const float* Wf2){
    int c = blockIdx.x;
    const float* src;
    if      (c < 9)  src = We1 + (size_t)(c/3)*384*ML + (size_t)(c%3)*128*128;
    else if (c < 12) src = We2 + (size_t)(c-9)*ML*ML;
    else if (c < 18) src = Wn1 + (size_t)((c-12)/2)*256*ML + (size_t)((c-12)%2)*128*128;
    else if (c < 21) src = Wn2 + (size_t)(c-18)*ML*ML;
    else if (c < 24) src = Wf1 + (size_t)(c-21)*128*128;
    else             src = Wf2;
    unsigned short* dp = wpk_buf + (size_t)c*32768;
    for (int idx = threadIdx.x; idx < 16384; idx += blockDim.x){
        int k = idx >> 7, n = idx & 127;
        float vv = src[(size_t)k*128 + n];
        __nv_bfloat16 h = __float2bfloat16_rn(vv);
        float rr = vv - __bfloat162float(h);
        __nv_bfloat16 l = __float2bfloat16_rn(rr);
        int kc = k >> 4, kk = k & 15;
        int r = kk >> 3, q = (kk >> 1) & 3, hh = kk & 1;
        int nt = n >> 3, lane = ((n & 7) << 2) + q;
        size_t base = ((size_t)((kc*16 + nt)*32 + lane))*8;
        dp[base + r*2 + hh]     = *reinterpret_cast<unsigned short*>(&h);
        dp[base + 4 + r*2 + hh] = *reinterpret_cast<unsigned short*>(&l);
    }
}

// ================= unified multi-job GEMM =================
// flags: bit0 = OUTSPLIT, bit1 = HALFE row map, bit2 = EDGEIN staging
struct CJob {
    const unsigned short *PH, *PL, *B;
    const float *q0, *q1, *Wei;
    float *C;
    unsigned short *SH, *SL;
    int nblocks, M, flags;
};
struct CJobs { CJob j[3]; };

__global__ void __launch_bounds__(256,2) tcg_jobs(CJobs js){
    extern __shared__ unsigned short As[];
    int b = blockIdx.x;
    CJob J;
    if (b < js.j[0].nblocks) J = js.j[0];
    else {
        b -= js.j[0].nblocks;
        if (b < js.j[1].nblocks) J = js.j[1];
        else { b -= js.j[1].nblocks; J = js.j[2]; }
    }
    const int tid = threadIdx.x, wid = tid >> 5, lane = tid & 31;
    const int row0 = (J.flags & 2) ? (b/125)*EPGC + (b%125)*128 : b*128;
    const int mq = wid & 1, nh = wid >> 1;

    const uint32_t sbase = smem_u32(As);
    const uint32_t a_h0 = sbase + ((mq*64 + (lane & 15))*AST + (lane >> 4)*8) * 2;
    const uint32_t a_l0 = a_h0 + SM_ALO_OFF*2;

    if (J.flags & 4){
        #pragma unroll 2
        for (int p = 0; p < 4; p++){
            int m  = p*32 + (tid >> 3);
            int c0 = (tid & 7) * 16;
            int grow = row0 + m; if (grow > J.M-1) grow = J.M-1;
            float sqt = selu_f(J.q0[grow]);
            float sqh = selu_f(J.q1[grow]);
            float w0[16], w1[16], vals[16];
            ld16(J.Wei + c0, w0);
            ld16(J.Wei + ML + c0, w1);
            #pragma unroll
            for (int j = 0; j < 16; j++) vals[j] = selu_f(sqt*w0[j] + sqh*w1[j]);
            unsigned hi2[8], lo2[8];
            split_pack(vals, hi2, lo2);
            unsigned short* dh_ = As + m*AST + c0;
            unsigned short* dl_ = dh_ + SM_ALO_OFF;
            *(uint4*)(dh_)     = make_uint4(hi2[0], hi2[1], hi2[2], hi2[3]);
            *(uint4*)(dh_ + 8) = make_uint4(hi2[4], hi2[5], hi2[6], hi2[7]);
            *(uint4*)(dl_)     = make_uint4(lo2[0], lo2[1], lo2[2], lo2[3]);
            *(uint4*)(dl_ + 8) = make_uint4(lo2[4], lo2[5], lo2[6], lo2[7]);
        }
    } else {
        #pragma unroll
        for (int p = 0; p < 4; p++){
            int m  = p*32 + (tid >> 3);
            int c0 = (tid & 7) * 16;
            int grow = row0 + m; if (grow > J.M-1) grow = J.M-1;
            uint32_t dh_ = sbase + (m*AST + c0)*2;
            uint32_t dl_ = dh_ + SM_ALO_OFF*2;
            const unsigned short* ph = J.PH + (size_t)grow*ML + c0;
            const unsigned short* pl = J.PL + (size_t)grow*ML + c0;
            cp_async16(dh_,      ph);
            cp_async16(dh_ + 16, ph + 8);
            cp_async16(dl_,      pl);
            cp_async16(dl_ + 16, pl + 8);
        }
        cp_async_wait_all();
    }
    __syncthreads();

    float acc[4][4][4];
    #pragma unroll
    for (int i = 0; i < 4; i++)
        #pragma unroll
        for (int j = 0; j < 4; j++)
            #pragma unroll
            for (int t = 0; t < 4; t++) acc[i][j][t] = 0.f;

    const uint4* Bw = (const uint4*)J.B;
    #pragma unroll 1
    for (int kc = 0; kc < 8; kc++){
        uint4 bq[4];
        #pragma unroll
        for (int j = 0; j < 4; j++)
            bq[j] = Bw[(size_t)((kc*16 + nh*4 + j)*32 + lane)];
        #pragma unroll
        for (int i = 0; i < 4; i++){
            unsigned ah[4], al[4];
            ldsm_x4(ah, a_h0 + kc*32 + i*(16*AST*2));
            ldsm_x4(al, a_l0 + kc*32 + i*(16*AST*2));
            #pragma unroll
            for (int j = 0; j < 4; j++){
                mma16816(acc[i][j], ah, bq[j].x, bq[j].y);
                mma16816(acc[i][j], ah, bq[j].z, bq[j].w);
                mma16816(acc[i][j], al, bq[j].x, bq[j].y);
            }
        }
    }

    const int rb = row0 + mq*64 + (lane >> 2);
    const int cb = nh*32 + (lane & 3)*2;
    const bool outsplit = J.flags & 1;
    #pragma unroll
    for (int i = 0; i < 4; i++){
        #pragma unroll
        for (int h = 0; h < 2; h++){
            int row = rb + i*16 + h*8;
            if (row >= J.M) continue;
            if (outsplit){
                #pragma unroll
                for (int j = 0; j < 4; j++){
                    float a0 = selu_f(acc[i][j][2*h]);
                    float a1 = selu_f(acc[i][j][2*h+1]);
                    unsigned short h0,l0,h1,l1;
                    split1(a0, h0, l0); split1(a1, h1, l1);
                    size_t o = (size_t)row*ML + cb + j*8;
                    *(ushort2*)(J.SH + o) = make_ushort2(h0, h1);
                    *(ushort2*)(J.SL + o) = make_ushort2(l0, l1);
                }
            } else {
                float* cp = J.C + (size_t)row*ML + cb;
                #pragma unroll
                for (int j = 0; j < 4; j++)
                    *(float2*)(cp + j*8) = make_float2(acc[i][j][2*h], acc[i][j][2*h+1]);
            }
        }
    }
}

// ================= templated GEMM (EDGEIN / SUM3 / CAT2D) =================
enum { M_SUM3=2, M_CAT2D=3, M_EDGEIN=4 };

template<int NCHUNK, int MODE, bool OUTACT, bool AGGMAX, bool DOTOUT, bool HALFE, bool OUTSPLIT>
__global__ void __launch_bounds__(256,2) tcg(
    const float* __restrict__ A0, const float* __restrict__ A1,
    const float* __restrict__ A2, const unsigned* __restrict__ AU,
    const unsigned short* __restrict__ PH, const unsigned short* __restrict__ PL,
    const int* __restrict__ iS, const int* __restrict__ iR,
    const unsigned short* __restrict__ Bpk,
    float* __restrict__ C,
    unsigned short* __restrict__ SH, unsigned short* __restrict__ SL,
    unsigned* __restrict__ aggU, const int* __restrict__ rcv,
    const float* __restrict__ Wf3, float* __restrict__ qout, int M, int skipz2)
{
    extern __shared__ unsigned short As[];
    const int tid = threadIdx.x, wid = tid >> 5, lane = tid & 31;
    const int row0 = HALFE ? (blockIdx.x/125)*EPGC + (blockIdx.x%125)*128
                           : blockIdx.x*128;
    const int mq = wid & 1, nh = wid >> 1;

    const uint32_t sbase = smem_u32(As);
    const uint32_t a_h0 = sbase + ((mq*64 + (lane & 15))*AST + (lane >> 4)*8) * 2;
    const uint32_t a_l0 = a_h0 + SM_ALO_OFF*2;

    float acc[4][4][4];
    #pragma unroll
    for (int i = 0; i < 4; i++)
        #pragma unroll
        for (int j = 0; j < 4; j++)
            #pragma unroll
            for (int t = 0; t < 4; t++) acc[i][j][t] = 0.f;

    #pragma unroll 1
    for (int ch = 0; ch < NCHUNK; ch++){
        if (MODE == M_CAT2D && ch == 0){
            #pragma unroll
            for (int p = 0; p < 4; p++){
                int m  = p*32 + (tid >> 3);
                int c0 = (tid & 7) * 16;
                int grow = row0 + m; if (grow > M-1) grow = M-1;
                uint32_t dh_ = sbase + (m*AST + c0)*2;
                uint32_t dl_ = dh_ + SM_ALO_OFF*2;
                const unsigned short* ph = PH + (size_t)grow*ML + c0;
                const unsigned short* pl = PL + (size_t)grow*ML + c0;
                cp_async16(dh_,      ph);
                cp_async16(dh_ + 16, ph + 8);
                cp_async16(dl_,      pl);
                cp_async16(dl_ + 16, pl + 8);
            }
            cp_async_wait_all();
        } else {
            #pragma unroll 2
            for (int p = 0; p < 4; p++){
                int m  = p*32 + (tid >> 3);
                int c0 = (tid & 7) * 16;
                int grow = row0 + m;
                bool canon = (grow <= M-1);
                if (!canon) grow = M-1;
                unsigned short* dh_ = As + m*AST + c0;
                unsigned short* dl_ = dh_ + SM_ALO_OFF;
                float vals[16];
                if (MODE == M_SUM3){
                    const float* pa = A0 + (size_t)iS[grow]*ML + c0;
                    const float* pb = A1 + (size_t)iR[grow]*ML + c0;
                    const float* pc = A2 + (size_t)grow*ML + c0;
                    float va[16], vb[16], vc[16];
                    ld16(pa, va); ld16(pb, vb); ld16(pc, vc);
                    #pragma unroll
                    for (int j = 0; j < 16; j++) vals[j] = selu_f(va[j] + vb[j] + vc[j]);
                } else if (MODE == M_EDGEIN){
                    float sqt = selu_f(A0[grow]);
                    float sqh = selu_f(A2[grow]);
                    float w0[16], w1[16];
                    ld16(A1 + c0, w0);
                    ld16(A1 + ML + c0, w1);
                    #pragma unroll
                    for (int j = 0; j < 16; j++) vals[j] = selu_f(sqt*w0[j] + sqh*w1[j]);
                } else { // M_CAT2D ch1
                    const unsigned* pu = AU + (size_t)grow*ML + c0;
                    uint4* pw = (uint4*)const_cast<unsigned*>(pu);
                    #pragma unroll
                    for (int i = 0; i < 4; i++){
                        uint4 t = *(const uint4*)(pu + 4*i);
                        if (canon)
                            pw[i] = make_uint4(ENC_NEGINF,ENC_NEGINF,ENC_NEGINF,ENC_NEGINF);
                        unsigned uu[4] = {t.x, t.y, t.z, t.w};
                        #pragma unroll
                        for (int j = 0; j < 4; j++){
                            float d = (uu[j] == ENC_NEGINF) ? 0.f : fdec(uu[j]);
                            vals[4*i + j] = selu_f(d);
                        }
                    }
                }
                unsigned hi2[8], lo2[8];
                split_pack(vals, hi2, lo2);
                *(uint4*)(dh_)     = make_uint4(hi2[0], hi2[1], hi2[2], hi2[3]);
                *(uint4*)(dh_ + 8) = make_uint4(hi2[4], hi2[5], hi2[6], hi2[7]);
                *(uint4*)(dl_)     = make_uint4(lo2[0], lo2[1], lo2[2], lo2[3]);
                *(uint4*)(dl_ + 8) = make_uint4(lo2[4], lo2[5], lo2[6], lo2[7]);
            }
        }
        __syncthreads();

        const uint4* Bw = (const uint4*)(Bpk + (size_t)ch*32768);
        #pragma unroll 1
        for (int kc = 0; kc < 8; kc++){
            uint4 bq[4];
            #pragma unroll
            for (int j = 0; j < 4; j++)
                bq[j] = Bw[(size_t)((kc*16 + nh*4 + j)*32 + lane)];
            #pragma unroll
            for (int i = 0; i < 4; i++){
                unsigned ah[4], al[4];
                ldsm_x4(ah, a_h0 + kc*32 + i*(16*AST*2));
                ldsm_x4(al, a_l0 + kc*32 + i*(16*AST*2));
                #pragma unroll
                for (int j = 0; j < 4; j++){
                    mma16816(acc[i][j], ah, bq[j].x, bq[j].y);
                    mma16816(acc[i][j], ah, bq[j].z, bq[j].w);
                    mma16816(acc[i][j], al, bq[j].x, bq[j].y);
                }
            }
        }
        __syncthreads();
    }

    const int rb = row0 + mq*64 + (lane >> 2);
    const int cb = nh*32 + (lane & 3)*2;
    #pragma unroll
    for (int i = 0; i < 4; i++){
        #pragma unroll
        for (int h = 0; h < 2; h++){
            int row = rb + i*16 + h*8;
            bool valid = row < M;
            float f[8];
            #pragma unroll
            for (int j = 0; j < 4; j++){
                f[2*j]   = acc[i][j][2*h];
                f[2*j+1] = acc[i][j][2*h+1];
                if (OUTACT){ f[2*j] = selu_f(f[2*j]); f[2*j+1] = selu_f(f[2*j+1]); }
            }
            if (DOTOUT){
                float s = 0.f;
                #pragma unroll
                for (int j = 0; j < 4; j++){
                    float2 wv = *(const float2*)(Wf3 + cb + j*8);
                    s += f[2*j]*wv.x + f[2*j+1]*wv.y;
                }
                s += __shfl_xor_sync(0xffffffffu, s, 1);
                s += __shfl_xor_sync(0xffffffffu, s, 2);
                if ((lane & 3) == 0 && valid) atomicAdd(qout + row, s);
            } else if (valid){
                if (AGGMAX){
                    unsigned* ap = aggU + (size_t)rcv[row]*ML + cb;
                    #pragma unroll
                    for (int j = 0; j < 4; j++){
                        atomicMax(ap + j*8,     fenc(f[2*j]));
                        atomicMax(ap + j*8 + 1, fenc(f[2*j+1]));
                    }
                }
                if (OUTSPLIT){
                    if (skipz2 && (row % EPGC) >= E2C) continue;
                    #pragma unroll
                    for (int j = 0; j < 4; j++){
                        float a0 = OUTACT ? f[2*j]   : selu_f(f[2*j]);
                        float a1 = OUTACT ? f[2*j+1] : selu_f(f[2*j+1]);
                        unsigned short h0,l0,h1,l1;
                        split1(a0, h0, l0); split1(a1, h1, l1);
                        size_t o = (size_t)row*ML + cb + j*8;
                        *(ushort2*)(SH + o) = make_ushort2(h0, h1);
                        *(ushort2*)(SL + o) = make_ushort2(l0, l1);
                    }
                } else if (C){
                    float* cp = C + (size_t)row*ML + cb;
                    #pragma unroll
                    for (int j = 0; j < 4; j++)
                        *(float2*)(cp + j*8) = make_float2(f[2*j], f[2*j+1]);
                }
            }
        }
    }
}

// ---------------- elementwise / segment kernels ----------------
__global__ void k_init(const float* __restrict__ x, float* __restrict__ hA,
                       float* __restrict__ dh, unsigned* __restrict__ agS,
                       unsigned* __restrict__ agu){
    int i = blockIdx.x*blockDim.x + threadIdx.x;
    if (i < NN*ML) agu[i] = ENC_NEGINF;
    if (i < NN){
        dh[i] = 0.f;
        hA[i] = x[2*i];
        agS[i] = ENC_NEGINF;
    }
}
__global__ void k_copy(const float* __restrict__ a, float* __restrict__ b, int n){
    int i = blockIdx.x*blockDim.x + threadIdx.x;
    if (i < n) b[i] = a[i];
}
__global__ void k_flows(const float* __restrict__ h, const float* __restrict__ r,
                        const int* __restrict__ s, const int* __restrict__ rc,
                        float* __restrict__ q, float* __restrict__ q2){
    int e = blockIdx.x*blockDim.x + threadIdx.x;
    if (e >= EE) return;
    float dh = h[s[e]] - h[rc[e]];
    float qe = signf(dh) * __powf((fabsf(dh) + ZETA) / (r[e] + ZETA), INVP);
    q[e] = qe;
    if (q2) q2[e] = qe;
}
__global__ void k_segsum(const float* __restrict__ q, const int* __restrict__ rc,
                         float* __restrict__ d){
    int e = blockIdx.x*blockDim.x + threadIdx.x;
    if (e < EE) atomicAdd(&d[rc[e]], q[e]);
}
// g = selu([d_hat, d_star])@Wni -> split(selu(g)); consumes dh and resets it to 0.
// NN*ML == 5,120,000 is an exact multiple of 256, so all threads reach __syncthreads.
__global__ void k_node_in(float* __restrict__ dh, const float* __restrict__ x,
                          const float* __restrict__ W,
                          unsigned short* __restrict__ GH, unsigned short* __restrict__ GL){
    int idx = blockIdx.x*blockDim.x + threadIdx.x;
    int n = idx >> 7, j = idx & 127;
    float dval = dh[n];
    __syncthreads();
    if (j == 0) dh[n] = 0.f;
    float gv = selu_f(dval) * W[j] + selu_f(x[2*n+1]) * W[ML + j];
    float sg = selu_f(gv);
    unsigned short h, l;
    split1(sg, h, l);
    GH[idx] = h; GL[idx] = l;
}
// fused per-edge: antisym q_hat + hl + segment-sum into dh (pre-zeroed by k_node_in);
// per-node: hA = h_star
__global__ void k_misc(float* __restrict__ qh, const float* __restrict__ r,
                       const float* __restrict__ x, const int* __restrict__ rc,
                       float* __restrict__ hl, float* __restrict__ dh,
                       float* __restrict__ hA){
    int i = blockIdx.x*blockDim.x + threadIdx.x;
    if (i < EE){
        int loc = i % EPGC;
        float qe;
        if (loc >= E2C){ qe = -qh[i - E2C]; qh[i] = qe; }
        else            qe = qh[i];
        atomicAdd(&dh[rc[i]], qe);
        float aq = fabsf(qe);
        float p  = (aq < 1e-30f) ? 0.f : __powf(aq, PEXP);
        hl[i] = r[i] * signf(qe) * p;
    }
    if (i < NN) hA[i] = x[2*i];
}
__global__ void k_head_edge(const float* __restrict__ h, const float* __restrict__ hl,
                            const int* __restrict__ s, const int* __restrict__ rc,
                            unsigned* __restrict__ agg){
    int e = blockIdx.x*blockDim.x + threadIdx.x;
    if (e < EE) atomicMax(&agg[rc[e]], fenc(h[s[e]] - hl[e]));
}
__global__ void k_head_node(unsigned* __restrict__ agg, const float* __restrict__ hold,
                            const float* __restrict__ x, float* __restrict__ hnew){
    int n = blockIdx.x*blockDim.x + threadIdx.x;
    if (n >= NN) return;
    float hs = x[2*n];
    unsigned u = agg[n];
    agg[n] = ENC_NEGINF;
    float a = (u == ENC_NEGINF) ? -INFINITY : fdec(u);
    hnew[n] = (hs != 0.f) ? hs : fmaxf(hold[n], a);
}

// ---------------- host orchestration ----------------
template<typename T>
static T* sym_addr(const void* sym){
    void* p = nullptr;
    cudaGetSymbolAddress(&p, sym);
    return (T*)p;
}
static void set_smem(const void* f){
    cudaFuncSetAttribute(f, cudaFuncAttributeMaxDynamicSharedMemorySize, SM_TOT);
}

extern "C" void kernel_launch(void* const* d_in, const int* in_sizes, int n_in,
                              void* d_out, int out_size)
{
    const float* x    = (const float*)d_in[0];
    const float* r    = (const float*)d_in[1];
    const float* Wni  = (const float*)d_in[2];
    const float* Wei  = (const float*)d_in[3];
    const float* Wf1  = (const float*)d_in[4];
    const float* Wf2  = (const float*)d_in[5];
    const float* Wf3  = (const float*)d_in[6];
    const float* We1  = (const float*)d_in[7];
    const float* We2  = (const float*)d_in[8];
    const float* Wn1  = (const float*)d_in[9];
    const float* Wn2  = (const float*)d_in[10];
    const int*   sndr = (const int*)d_in[11];
    const int*   rcvr = (const int*)d_in[12];
    float*       out  = (float*)d_out;

    unsigned* agu = sym_addr<unsigned>(agg_buf);
    float*    u   = sym_addr<float>(u_buf);
    float*    v   = sym_addr<float>(v_buf);
    float*    w   = sym_addr<float>(w_buf);
    unsigned short* GH = sym_addr<unsigned short>(ghi_buf);
    unsigned short* GL = sym_addr<unsigned short>(glo_buf);
    unsigned short* ZH = sym_addr<unsigned short>(zhi_buf);
    unsigned short* ZL = sym_addr<unsigned short>(zlo_buf);
    unsigned short* TH2= sym_addr<unsigned short>(thi_buf);
    unsigned short* TL2= sym_addr<unsigned short>(tlo_buf);
    float*    qh  = sym_addr<float>(qh_buf);
    float*    qt  = sym_addr<float>(qt_buf);
    float*    hl  = sym_addr<float>(hl_buf);
    float*    dh  = sym_addr<float>(dh_buf);
    float*    hA  = sym_addr<float>(hA_buf);
    float*    hB  = sym_addr<float>(hB_buf);
    unsigned* agS = sym_addr<unsigned>(aggS_buf);
    unsigned short* WP = sym_addr<unsigned short>(wpk_buf);

    set_smem((const void*)tcg<1,M_EDGEIN,false,false,false,false,false>);
    set_smem((const void*)tcg<1,M_SUM3  ,false,true ,false,false,true >);
    set_smem((const void*)tcg<2,M_CAT2D ,true ,false,false,false,true >);
    set_smem((const void*)tcg<1,M_SUM3  ,true ,false,true ,true ,false>);
    set_smem((const void*)tcg_jobs);

    const int T = 256;
    const int gN  = (NN + T - 1) / T;
    const int gE  = (EE + T - 1) / T;
    const int gNM = (NN*ML) / T;     // exact: 20000

    const int TE = (EE + 127)/128;   // 1000
    const int TN = (NN + 127)/128;   // 313
    const int THF = 500;

    #define CHK(i) (WP + (size_t)(i)*32768)

    auto mkjob = [&](const unsigned short* PH, const unsigned short* PL,
                     const unsigned short* B, float* C,
                     unsigned short* SH, unsigned short* SL,
                     int nb, int M, int flags) -> CJob {
        CJob j; j.PH=PH; j.PL=PL; j.B=B; j.q0=nullptr; j.q1=nullptr; j.Wei=nullptr;
        j.C=C; j.SH=SH; j.SL=SL; j.nblocks=nb; j.M=M; j.flags=flags; return j;
    };
    auto mkedge = [&](const float* q0, const float* q1, const float* W,
                      const unsigned short* B, float* C, int nb) -> CJob {
        CJob j; j.PH=nullptr; j.PL=nullptr; j.B=B; j.q0=q0; j.q1=q1; j.Wei=W;
        j.C=C; j.SH=nullptr; j.SL=nullptr; j.nblocks=nb; j.M=EE; j.flags=4; return j;
    };
    CJob empty = mkjob(nullptr,nullptr,nullptr,nullptr,nullptr,nullptr,0,0,0);

    // ---- visible launches 0..3 (ncu captures visible idx 3 = EDGEIN) ----
    k_prep<<<25, 256>>>(We1, We2, Wn1, Wn2, Wf1, Wf2);          // 0
    k_init<<<gNM, T>>>(x, hA, dh, agS, agu);                    // 1
    k_flows<<<gE, T>>>(hA, r, sndr, rcvr, qh, qt);              // 2
    tcg<1,M_EDGEIN,false,false,false,false,false><<<TE, 256, SM_TOT>>>(   // 3 PROFILED
        qt, Wei, qh, nullptr, nullptr, nullptr, nullptr, nullptr,
        CHK(2), w, nullptr, nullptr, nullptr, nullptr, nullptr, nullptr, EE, 0);
    k_segsum<<<gE, T>>>(qh, rcvr, dh);
    k_node_in<<<gNM, T>>>(dh, x, Wni, GH, GL);                  // consumes + resets dh

    for (int k = 0; k < K_ITERS; k++){
        if (k > 0){
            k_node_in<<<gNM, T>>>(dh, x, Wni, GH, GL);
            CJobs js = {{ mkedge(qt, qh, Wei, CHK(2), w, TE),
                          mkjob(GH,GL,CHK(0),u,nullptr,nullptr,TN,NN,0),
                          mkjob(GH,GL,CHK(1),v,nullptr,nullptr,TN,NN,0) }};
            tcg_jobs<<<TE+2*TN, 256, SM_TOT>>>(js);
        } else {
            CJobs js = {{ mkjob(GH,GL,CHK(0),u,nullptr,nullptr,TN,NN,0),
                          mkjob(GH,GL,CHK(1),v,nullptr,nullptr,TN,NN,0),
                          empty }};
            tcg_jobs<<<2*TN, 256, SM_TOT>>>(js);
        }

        for (int i = 0; i < I_LAYERS; i++){
            tcg<1,M_SUM3,false,true,false,false,true><<<TE, 256, SM_TOT>>>(
                u, v, w, nullptr, nullptr, nullptr, sndr, rcvr,
                CHK(9+i), nullptr, ZH, ZL, agu, rcvr, nullptr, nullptr, EE, (i==2)?1:0);
            tcg<2,M_CAT2D,true,false,false,false,true><<<TN, 256, SM_TOT>>>(
                nullptr, nullptr, nullptr, agu, GH, GL, nullptr, nullptr,
                CHK(12+2*i), nullptr, TH2, TL2, nullptr, nullptr, nullptr, nullptr, NN, 0);
            if (i < 2){
                CJobs js = {{ mkjob(TH2,TL2,CHK(18+i),nullptr,GH,GL,TN,NN,1),
                              mkjob(ZH,ZL,CHK((i+1)*3+2),w,nullptr,nullptr,TE,EE,0),
                              empty }};
                tcg_jobs<<<TN+TE, 256, SM_TOT>>>(js);
                CJobs js2 = {{ mkjob(GH,GL,CHK((i+1)*3),u,nullptr,nullptr,TN,NN,0),
                               mkjob(GH,GL,CHK((i+1)*3+1),v,nullptr,nullptr,TN,NN,0),
                               empty }};
                tcg_jobs<<<2*TN, 256, SM_TOT>>>(js2);
            } else {
                CJobs js = {{ mkjob(TH2,TL2,CHK(18+i),nullptr,GH,GL,TN,NN,1),
                              empty, empty }};
                tcg_jobs<<<TN, 256, SM_TOT>>>(js);
            }
        }

        // flow head
        {
            CJobs js = {{ mkjob(GH,GL,CHK(21),u,nullptr,nullptr,TN,NN,0),
                          mkjob(GH,GL,CHK(22),v,nullptr,nullptr,TN,NN,0),
                          mkjob(ZH,ZL,CHK(23),w,nullptr,nullptr,THF,EE,2) }};
            tcg_jobs<<<2*TN+THF, 256, SM_TOT>>>(js);
        }
        tcg<1,M_SUM3,true,false,true,true,false><<<THF, 256, SM_TOT>>>(
            u, v, w, nullptr, nullptr, nullptr, sndr, rcvr,
            CHK(24), nullptr, nullptr, nullptr, nullptr, nullptr, Wf3, qh, EE, 0);

        // fused antisym + hl + segment-sum + hA
        k_misc<<<gE, T>>>(qh, r, x, rcvr, hl, dh, hA);

        // construct_heads (atomic agS, self-resetting)
        float* hc = hA; float* hn = hB;
        for (int j = 0; j < J_HEADS; j++){
            k_head_edge<<<gE, T>>>(hc, hl, sndr, rcvr, agS);
            k_head_node<<<gN, T>>>(agS, hc, x, hn);
            float* t2 = hc; hc = hn; hn = t2;
        }

        k_flows<<<gE, T>>>(hc, r, sndr, rcvr, qt, nullptr);
    }

    k_copy<<<gN, T>>>(hA, out, NN);
    (void)in_sizes; (void)n_in; (void)out_size;
    #undef CHK
}

// round 14
// speedup vs baseline: 1.0375x; 1.0271x over previous
#include <cuda_runtime.h>
#include <cuda_bf16.h>
#include <math.h>
#include <stdint.h>

// ---------------- problem constants ----------------
#define NN   40000
#define EE   128000
#define E2C  16000
#define EPGC 32000
#define BC   4
#define ML   128
#define ZETA 1e-6f
#define PEXP 1.852f
#define INVP (1.0f/1.852f)
#define I_LAYERS 3
#define K_ITERS  4
#define J_HEADS  6

#define SELU_SCALE 1.0507009873554805f
#define SELU_ALPHA 1.6732632423543772f
#define ENC_NEGINF 0x007FFFFFu

// A tile in smem: 64 rows x 136 (padded) bf16, hi + lo; 128-thread blocks
#define TR   64
#define AST  136
#define SM_ALO_OFF (TR*AST)
#define SM_TOT (2*TR*AST*2)    // 34816 bytes -> 4 CTAs/SM

// ---------------- device scratch ----------------
__device__ unsigned agg_buf[NN*ML];
__device__ float    u_buf[NN*ML];
__device__ float    v_buf[NN*ML];
__device__ float    w_buf[(size_t)EE*ML];
__device__ unsigned short ghi_buf[NN*ML],  glo_buf[NN*ML];
__device__ unsigned short zhi_buf[(size_t)EE*ML], zlo_buf[(size_t)EE*ML];
__device__ unsigned short thi_buf[NN*ML],  tlo_buf[NN*ML];
__device__ float    qh_buf[EE];
__device__ float    qt_buf[EE];
__device__ float    hl_buf[EE];
__device__ float    dh_buf[NN];
__device__ float    hA_buf[NN];
__device__ float    hB_buf[NN];
__device__ unsigned aggS_buf[NN];
__device__ unsigned short wpk_buf[(size_t)25*32768];

// ---------------- scalar helpers ----------------
__device__ __forceinline__ float selu_f(float x){
    return x > 0.f ? SELU_SCALE * x : SELU_SCALE * SELU_ALPHA * (__expf(x) - 1.f);
}
__device__ __forceinline__ unsigned fenc(float f){
    unsigned u = __float_as_uint(f);
    return (u >> 31) ? ~u : (u | 0x80000000u);
}
__device__ __forceinline__ float fdec(unsigned u){
    return (u >> 31) ? __uint_as_float(u & 0x7fffffffu) : __uint_as_float(~u);
}
__device__ __forceinline__ float signf(float x){
    return (x > 0.f) ? 1.f : ((x < 0.f) ? -1.f : 0.f);
}
__device__ __forceinline__ void mma16816(float* d, const unsigned* a, unsigned b0, unsigned b1){
    asm volatile("mma.sync.aligned.m16n8k16.row.col.f32.bf16.bf16.f32 "
        "{%0,%1,%2,%3}, {%4,%5,%6,%7}, {%8,%9}, {%0,%1,%2,%3};"
        : "+f"(d[0]), "+f"(d[1]), "+f"(d[2]), "+f"(d[3])
        : "r"(a[0]), "r"(a[1]), "r"(a[2]), "r"(a[3]), "r"(b0), "r"(b1));
}
__device__ __forceinline__ void ldsm_x4(unsigned* r, uint32_t addr){
    asm volatile("ldmatrix.sync.aligned.m8n8.x4.shared.b16 {%0,%1,%2,%3}, [%4];"
        : "=r"(r[0]), "=r"(r[1]), "=r"(r[2]), "=r"(r[3]) : "r"(addr));
}
__device__ __forceinline__ uint32_t smem_u32(const void* p){
    uint32_t a;
    asm("{ .reg .u64 t; cvta.to.shared.u64 t, %1; cvt.u32.u64 %0, t; }" : "=r"(a) : "l"(p));
    return a;
}
__device__ __forceinline__ void cp_async16(uint32_t dst, const void* src){
    asm volatile("cp.async.ca.shared.global [%0], [%1], 16;" :: "r"(dst), "l"(src));
}
__device__ __forceinline__ void cp_async_wait_all(){
    asm volatile("cp.async.commit_group;\n\tcp.async.wait_group 0;" ::: "memory");
}
__device__ __forceinline__ void ld16(const float* p, float* v){
    #pragma unroll
    for (int i = 0; i < 4; i++){
        float4 t = *(const float4*)(p + 4*i);
        v[4*i]=t.x; v[4*i+1]=t.y; v[4*i+2]=t.z; v[4*i+3]=t.w;
    }
}
__device__ __forceinline__ void split_pack(const float* vals, unsigned* hi2, unsigned* lo2){
    #pragma unroll
    for (int j = 0; j < 8; j++){
        float a = vals[2*j], b = vals[2*j+1];
        __nv_bfloat16 ha = __float2bfloat16_rn(a);
        __nv_bfloat16 hb = __float2bfloat16_rn(b);
        float ra = a - __bfloat162float(ha);
        float rb = b - __bfloat162float(hb);
        __nv_bfloat162 hp = __halves2bfloat162(ha, hb);
        __nv_bfloat162 lp = __halves2bfloat162(__float2bfloat16_rn(ra), __float2bfloat16_rn(rb));
        hi2[j] = *reinterpret_cast<unsigned*>(&hp);
        lo2[j] = *reinterpret_cast<unsigned*>(&lp);
    }
}
__device__ __forceinline__ void split1(float a, unsigned short& h, unsigned short& l){
    __nv_bfloat16 hb = __float2bfloat16_rn(a);
    float rr = a - __bfloat162float(hb);
    __nv_bfloat16 lb = __float2bfloat16_rn(rr);
    h = *reinterpret_cast<unsigned short*>(&hb);
    l = *reinterpret_cast<unsigned short*>(&lb);
}

// ---------------- weight prep ----------------
__global__ void k_prep(const float* We1, const float* We2, const float* Wn1,
                       const float* Wn2, const float* Wf1, const float* Wf2){
    int c = blockIdx.x;
    const float* src;
    if      (c < 9)  src = We1 + (size_t)(c/3)*384*ML + (size_t)(c%3)*128*128;
    else if (c < 12) src = We2 + (size_t)(c-9)*ML*ML;
    else if (c < 18) src = Wn1 + (size_t)((c-12)/2)*256*ML + (size_t)((c-12)%2)*128*128;
    else if (c < 21) src = Wn2 + (size_t)(c-18)*ML*ML;
    else if (c < 24) src = Wf1 + (size_t)(c-21)*128*128;
    else             src = Wf2;
    unsigned short* dp = wpk_buf + (size_t)c*32768;
    for (int idx = threadIdx.x; idx < 16384; idx += blockDim.x){
        int k = idx >> 7, n = idx & 127;
        float vv = src[(size_t)k*128 + n];
        __nv_bfloat16 h = __float2bfloat16_rn(vv);
        float rr = vv - __bfloat162float(h);
        __nv_bfloat16 l = __float2bfloat16_rn(rr);
        int kc = k >> 4, kk = k & 15;
        int r = kk >> 3, q = (kk >> 1) & 3, hh = kk & 1;
        int nt = n >> 3, lane = ((n & 7) << 2) + q;
        size_t base = ((size_t)((kc*16 + nt)*32 + lane))*8;
        dp[base + r*2 + hh]     = *reinterpret_cast<unsigned short*>(&h);
        dp[base + 4 + r*2 + hh] = *reinterpret_cast<unsigned short*>(&l);
    }
}

// ================= unified multi-job GEMM (64-row tiles, 128 threads) =================
// flags: bit0 = OUTSPLIT, bit1 = HALFE row map, bit2 = EDGEIN staging
struct CJob {
    const unsigned short *PH, *PL, *B;
    const float *q0, *q1, *Wei;
    float *C;
    unsigned short *SH, *SL;
    int nblocks, M, flags;
};
struct CJobs { CJob j[3]; };

__global__ void __launch_bounds__(128,4) tcg_jobs(CJobs js){
    extern __shared__ unsigned short As[];
    int b = blockIdx.x;
    CJob J;
    if (b < js.j[0].nblocks) J = js.j[0];
    else {
        b -= js.j[0].nblocks;
        if (b < js.j[1].nblocks) J = js.j[1];
        else { b -= js.j[1].nblocks; J = js.j[2]; }
    }
    const int tid = threadIdx.x, nh = tid >> 5, lane = tid & 31;
    const int row0 = (J.flags & 2) ? (b/250)*EPGC + (b%250)*TR : b*TR;

    const uint32_t sbase = smem_u32(As);
    const uint32_t a_h0 = sbase + ((lane & 15)*AST + (lane >> 4)*8) * 2;
    const uint32_t a_l0 = a_h0 + SM_ALO_OFF*2;

    if (J.flags & 4){
        #pragma unroll 2
        for (int p = 0; p < 4; p++){
            int m  = p*16 + (tid >> 3);
            int c0 = (tid & 7) * 16;
            int grow = row0 + m; if (grow > J.M-1) grow = J.M-1;
            float sqt = selu_f(J.q0[grow]);
            float sqh = selu_f(J.q1[grow]);
            float w0[16], w1[16], vals[16];
            ld16(J.Wei + c0, w0);
            ld16(J.Wei + ML + c0, w1);
            #pragma unroll
            for (int j = 0; j < 16; j++) vals[j] = selu_f(sqt*w0[j] + sqh*w1[j]);
            unsigned hi2[8], lo2[8];
            split_pack(vals, hi2, lo2);
            unsigned short* dh_ = As + m*AST + c0;
            unsigned short* dl_ = dh_ + SM_ALO_OFF;
            *(uint4*)(dh_)     = make_uint4(hi2[0], hi2[1], hi2[2], hi2[3]);
            *(uint4*)(dh_ + 8) = make_uint4(hi2[4], hi2[5], hi2[6], hi2[7]);
            *(uint4*)(dl_)     = make_uint4(lo2[0], lo2[1], lo2[2], lo2[3]);
            *(uint4*)(dl_ + 8) = make_uint4(lo2[4], lo2[5], lo2[6], lo2[7]);
        }
    } else {
        #pragma unroll
        for (int p = 0; p < 4; p++){
            int m  = p*16 + (tid >> 3);
            int c0 = (tid & 7) * 16;
            int grow = row0 + m; if (grow > J.M-1) grow = J.M-1;
            uint32_t dh_ = sbase + (m*AST + c0)*2;
            uint32_t dl_ = dh_ + SM_ALO_OFF*2;
            const unsigned short* ph = J.PH + (size_t)grow*ML + c0;
            const unsigned short* pl = J.PL + (size_t)grow*ML + c0;
            cp_async16(dh_,      ph);
            cp_async16(dh_ + 16, ph + 8);
            cp_async16(dl_,      pl);
            cp_async16(dl_ + 16, pl + 8);
        }
        cp_async_wait_all();
    }
    __syncthreads();

    float acc[4][4][4];
    #pragma unroll
    for (int i = 0; i < 4; i++)
        #pragma unroll
        for (int j = 0; j < 4; j++)
            #pragma unroll
            for (int t = 0; t < 4; t++) acc[i][j][t] = 0.f;

    const uint4* Bw = (const uint4*)J.B;
    #pragma unroll 1
    for (int kc = 0; kc < 8; kc++){
        uint4 bq[4];
        #pragma unroll
        for (int j = 0; j < 4; j++)
            bq[j] = Bw[(size_t)((kc*16 + nh*4 + j)*32 + lane)];
        #pragma unroll
        for (int i = 0; i < 4; i++){
            unsigned ah[4], al[4];
            ldsm_x4(ah, a_h0 + kc*32 + i*(16*AST*2));
            ldsm_x4(al, a_l0 + kc*32 + i*(16*AST*2));
            #pragma unroll
            for (int j = 0; j < 4; j++){
                mma16816(acc[i][j], ah, bq[j].x, bq[j].y);
                mma16816(acc[i][j], ah, bq[j].z, bq[j].w);
                mma16816(acc[i][j], al, bq[j].x, bq[j].y);
            }
        }
    }

    const int rb = row0 + (lane >> 2);
    const int cb = nh*32 + (lane & 3)*2;
    const bool outsplit = J.flags & 1;
    #pragma unroll
    for (int i = 0; i < 4; i++){
        #pragma unroll
        for (int h = 0; h < 2; h++){
            int row = rb + i*16 + h*8;
            if (row >= J.M) continue;
            if (outsplit){
                #pragma unroll
                for (int j = 0; j < 4; j++){
                    float a0 = selu_f(acc[i][j][2*h]);
                    float a1 = selu_f(acc[i][j][2*h+1]);
                    unsigned short h0,l0,h1,l1;
                    split1(a0, h0, l0); split1(a1, h1, l1);
                    size_t o = (size_t)row*ML + cb + j*8;
                    *(ushort2*)(J.SH + o) = make_ushort2(h0, h1);
                    *(ushort2*)(J.SL + o) = make_ushort2(l0, l1);
                }
            } else {
                float* cp = J.C + (size_t)row*ML + cb;
                #pragma unroll
                for (int j = 0; j < 4; j++)
                    *(float2*)(cp + j*8) = make_float2(acc[i][j][2*h], acc[i][j][2*h+1]);
            }
        }
    }
}

// ================= templated GEMM (EDGEIN / SUM3 / CAT2D) =================
enum { M_SUM3=2, M_CAT2D=3, M_EDGEIN=4 };

template<int NCHUNK, int MODE, bool OUTACT, bool AGGMAX, bool DOTOUT, bool HALFE, bool OUTSPLIT>
__global__ void __launch_bounds__(128,4) tcg(
    const float* __restrict__ A0, const float* __restrict__ A1,
    const float* __restrict__ A2, const unsigned* __restrict__ AU,
    const unsigned short* __restrict__ PH, const unsigned short* __restrict__ PL,
    const int* __restrict__ iS, const int* __restrict__ iR,
    const unsigned short* __restrict__ Bpk,
    float* __restrict__ C,
    unsigned short* __restrict__ SH, unsigned short* __restrict__ SL,
    unsigned* __restrict__ aggU, const int* __restrict__ rcv,
    const float* __restrict__ Wf3, float* __restrict__ qout, int M, int skipz2)
{
    extern __shared__ unsigned short As[];
    const int tid = threadIdx.x, nh = tid >> 5, lane = tid & 31;
    const int row0 = HALFE ? (blockIdx.x/250)*EPGC + (blockIdx.x%250)*TR
                           : blockIdx.x*TR;

    const uint32_t sbase = smem_u32(As);
    const uint32_t a_h0 = sbase + ((lane & 15)*AST + (lane >> 4)*8) * 2;
    const uint32_t a_l0 = a_h0 + SM_ALO_OFF*2;

    float acc[4][4][4];
    #pragma unroll
    for (int i = 0; i < 4; i++)
        #pragma unroll
        for (int j = 0; j < 4; j++)
            #pragma unroll
            for (int t = 0; t < 4; t++) acc[i][j][t] = 0.f;

    #pragma unroll 1
    for (int ch = 0; ch < NCHUNK; ch++){
        if (MODE == M_CAT2D && ch == 0){
            #pragma unroll
            for (int p = 0; p < 4; p++){
                int m  = p*16 + (tid >> 3);
                int c0 = (tid & 7) * 16;
                int grow = row0 + m; if (grow > M-1) grow = M-1;
                uint32_t dh_ = sbase + (m*AST + c0)*2;
                uint32_t dl_ = dh_ + SM_ALO_OFF*2;
                const unsigned short* ph = PH + (size_t)grow*ML + c0;
                const unsigned short* pl = PL + (size_t)grow*ML + c0;
                cp_async16(dh_,      ph);
                cp_async16(dh_ + 16, ph + 8);
                cp_async16(dl_,      pl);
                cp_async16(dl_ + 16, pl + 8);
            }
            cp_async_wait_all();
        } else {
            #pragma unroll 2
            for (int p = 0; p < 4; p++){
                int m  = p*16 + (tid >> 3);
                int c0 = (tid & 7) * 16;
                int grow = row0 + m;
                bool canon = (grow <= M-1);
                if (!canon) grow = M-1;
                unsigned short* dh_ = As + m*AST + c0;
                unsigned short* dl_ = dh_ + SM_ALO_OFF;
                float vals[16];
                if (MODE == M_SUM3){
                    const float* pa = A0 + (size_t)iS[grow]*ML + c0;
                    const float* pb = A1 + (size_t)iR[grow]*ML + c0;
                    const float* pc = A2 + (size_t)grow*ML + c0;
                    float va[16], vb[16], vc[16];
                    ld16(pa, va); ld16(pb, vb); ld16(pc, vc);
                    #pragma unroll
                    for (int j = 0; j < 16; j++) vals[j] = selu_f(va[j] + vb[j] + vc[j]);
                } else if (MODE == M_EDGEIN){
                    float sqt = selu_f(A0[grow]);
                    float sqh = selu_f(A2[grow]);
                    float w0[16], w1[16];
                    ld16(A1 + c0, w0);
                    ld16(A1 + ML + c0, w1);
                    #pragma unroll
                    for (int j = 0; j < 16; j++) vals[j] = selu_f(sqt*w0[j] + sqh*w1[j]);
                } else { // M_CAT2D ch1
                    const unsigned* pu = AU + (size_t)grow*ML + c0;
                    uint4* pw = (uint4*)const_cast<unsigned*>(pu);
                    #pragma unroll
                    for (int i = 0; i < 4; i++){
                        uint4 t = *(const uint4*)(pu + 4*i);
                        if (canon)
                            pw[i] = make_uint4(ENC_NEGINF,ENC_NEGINF,ENC_NEGINF,ENC_NEGINF);
                        unsigned uu[4] = {t.x, t.y, t.z, t.w};
                        #pragma unroll
                        for (int j = 0; j < 4; j++){
                            float d = (uu[j] == ENC_NEGINF) ? 0.f : fdec(uu[j]);
                            vals[4*i + j] = selu_f(d);
                        }
                    }
                }
                unsigned hi2[8], lo2[8];
                split_pack(vals, hi2, lo2);
                *(uint4*)(dh_)     = make_uint4(hi2[0], hi2[1], hi2[2], hi2[3]);
                *(uint4*)(dh_ + 8) = make_uint4(hi2[4], hi2[5], hi2[6], hi2[7]);
                *(uint4*)(dl_)     = make_uint4(lo2[0], lo2[1], lo2[2], lo2[3]);
                *(uint4*)(dl_ + 8) = make_uint4(lo2[4], lo2[5], lo2[6], lo2[7]);
            }
        }
        __syncthreads();

        const uint4* Bw = (const uint4*)(Bpk + (size_t)ch*32768);
        #pragma unroll 1
        for (int kc = 0; kc < 8; kc++){
            uint4 bq[4];
            #pragma unroll
            for (int j = 0; j < 4; j++)
                bq[j] = Bw[(size_t)((kc*16 + nh*4 + j)*32 + lane)];
            #pragma unroll
            for (int i = 0; i < 4; i++){
                unsigned ah[4], al[4];
                ldsm_x4(ah, a_h0 + kc*32 + i*(16*AST*2));
                ldsm_x4(al, a_l0 + kc*32 + i*(16*AST*2));
                #pragma unroll
                for (int j = 0; j < 4; j++){
                    mma16816(acc[i][j], ah, bq[j].x, bq[j].y);
                    mma16816(acc[i][j], ah, bq[j].z, bq[j].w);
                    mma16816(acc[i][j], al, bq[j].x, bq[j].y);
                }
            }
        }
        __syncthreads();
    }

    const int rb = row0 + (lane >> 2);
    const int cb = nh*32 + (lane & 3)*2;
    #pragma unroll
    for (int i = 0; i < 4; i++){
        #pragma unroll
        for (int h = 0; h < 2; h++){
            int row = rb + i*16 + h*8;
            bool valid = row < M;
            float f[8];
            #pragma unroll
            for (int j = 0; j < 4; j++){
                f[2*j]   = acc[i][j][2*h];
                f[2*j+1] = acc[i][j][2*h+1];
                if (OUTACT){ f[2*j] = selu_f(f[2*j]); f[2*j+1] = selu_f(f[2*j+1]); }
            }
            if (DOTOUT){
                float s = 0.f;
                #pragma unroll
                for (int j = 0; j < 4; j++){
                    float2 wv = *(const float2*)(Wf3 + cb + j*8);
                    s += f[2*j]*wv.x + f[2*j+1]*wv.y;
                }
                s += __shfl_xor_sync(0xffffffffu, s, 1);
                s += __shfl_xor_sync(0xffffffffu, s, 2);
                if ((lane & 3) == 0 && valid) atomicAdd(qout + row, s);
            } else if (valid){
                if (AGGMAX){
                    unsigned* ap = aggU + (size_t)rcv[row]*ML + cb;
                    #pragma unroll
                    for (int j = 0; j < 4; j++){
                        atomicMax(ap + j*8,     fenc(f[2*j]));
                        atomicMax(ap + j*8 + 1, fenc(f[2*j+1]));
                    }
                }
                if (OUTSPLIT){
                    if (skipz2 && (row % EPGC) >= E2C) continue;
                    #pragma unroll
                    for (int j = 0; j < 4; j++){
                        float a0 = OUTACT ? f[2*j]   : selu_f(f[2*j]);
                        float a1 = OUTACT ? f[2*j+1] : selu_f(f[2*j+1]);
                        unsigned short h0,l0,h1,l1;
                        split1(a0, h0, l0); split1(a1, h1, l1);
                        size_t o = (size_t)row*ML + cb + j*8;
                        *(ushort2*)(SH + o) = make_ushort2(h0, h1);
                        *(ushort2*)(SL + o) = make_ushort2(l0, l1);
                    }
                } else if (C){
                    float* cp = C + (size_t)row*ML + cb;
                    #pragma unroll
                    for (int j = 0; j < 4; j++)
                        *(float2*)(cp + j*8) = make_float2(f[2*j], f[2*j+1]);
                }
            }
        }
    }
}

// ---------------- elementwise / segment kernels ----------------
__global__ void k_init(const float* __restrict__ x, float* __restrict__ hA,
                       float* __restrict__ dh, unsigned* __restrict__ agS,
                       unsigned* __restrict__ agu){
    int i = blockIdx.x*blockDim.x + threadIdx.x;
    if (i < NN*ML) agu[i] = ENC_NEGINF;
    if (i < NN){
        dh[i] = 0.f;
        hA[i] = x[2*i];
        agS[i] = ENC_NEGINF;
    }
}
__global__ void k_copy(const float* __restrict__ a, float* __restrict__ b, int n){
    int i = blockIdx.x*blockDim.x + threadIdx.x;
    if (i < n) b[i] = a[i];
}
__global__ void k_flows(const float* __restrict__ h, const float* __restrict__ r,
                        const int* __restrict__ s, const int* __restrict__ rc,
                        float* __restrict__ q, float* __restrict__ q2){
    int e = blockIdx.x*blockDim.x + threadIdx.x;
    if (e >= EE) return;
    float dh = h[s[e]] - h[rc[e]];
    float qe = signf(dh) * __powf((fabsf(dh) + ZETA) / (r[e] + ZETA), INVP);
    q[e] = qe;
    if (q2) q2[e] = qe;
}
__global__ void k_segsum(const float* __restrict__ q, const int* __restrict__ rc,
                         float* __restrict__ d){
    int e = blockIdx.x*blockDim.x + threadIdx.x;
    if (e < EE) atomicAdd(&d[rc[e]], q[e]);
}
// g = selu([d_hat, d_star])@Wni -> split(selu(g)); consumes dh and resets it to 0.
__global__ void k_node_in(float* __restrict__ dh, const float* __restrict__ x,
                          const float* __restrict__ W,
                          unsigned short* __restrict__ GH, unsigned short* __restrict__ GL){
    int idx = blockIdx.x*blockDim.x + threadIdx.x;
    int n = idx >> 7, j = idx & 127;
    float dval = dh[n];
    __syncthreads();
    if (j == 0) dh[n] = 0.f;
    float gv = selu_f(dval) * W[j] + selu_f(x[2*n+1]) * W[ML + j];
    float sg = selu_f(gv);
    unsigned short h, l;
    split1(sg, h, l);
    GH[idx] = h; GL[idx] = l;
}
// fused per-edge: antisym + hl + segment-sum into dh; per-node: hA = h_star
__global__ void k_misc(float* __restrict__ qh, const float* __restrict__ r,
                       const float* __restrict__ x, const int* __restrict__ rc,
                       float* __restrict__ hl, float* __restrict__ dh,
                       float* __restrict__ hA){
    int i = blockIdx.x*blockDim.x + threadIdx.x;
    if (i < EE){
        int loc = i % EPGC;
        float qe;
        if (loc >= E2C){ qe = -qh[i - E2C]; qh[i] = qe; }
        else            qe = qh[i];
        atomicAdd(&dh[rc[i]], qe);
        float aq = fabsf(qe);
        float p  = (aq < 1e-30f) ? 0.f : __powf(aq, PEXP);
        hl[i] = r[i] * signf(qe) * p;
    }
    if (i < NN) hA[i] = x[2*i];
}
__global__ void k_head_edge(const float* __restrict__ h, const float* __restrict__ hl,
                            const int* __restrict__ s, const int* __restrict__ rc,
                            unsigned* __restrict__ agg){
    int e = blockIdx.x*blockDim.x + threadIdx.x;
    if (e < EE) atomicMax(&agg[rc[e]], fenc(h[s[e]] - hl[e]));
}
__global__ void k_head_node(unsigned* __restrict__ agg, const float* __restrict__ hold,
                            const float* __restrict__ x, float* __restrict__ hnew){
    int n = blockIdx.x*blockDim.x + threadIdx.x;
    if (n >= NN) return;
    float hs = x[2*n];
    unsigned u = agg[n];
    agg[n] = ENC_NEGINF;
    float a = (u == ENC_NEGINF) ? -INFINITY : fdec(u);
    hnew[n] = (hs != 0.f) ? hs : fmaxf(hold[n], a);
}

// ---------------- host orchestration ----------------
template<typename T>
static T* sym_addr(const void* sym){
    void* p = nullptr;
    cudaGetSymbolAddress(&p, sym);
    return (T*)p;
}
static void set_smem(const void* f){
    cudaFuncSetAttribute(f, cudaFuncAttributeMaxDynamicSharedMemorySize, SM_TOT);
}

extern "C" void kernel_launch(void* const* d_in, const int* in_sizes, int n_in,
                              void* d_out, int out_size)
{
    const float* x    = (const float*)d_in[0];
    const float* r    = (const float*)d_in[1];
    const float* Wni  = (const float*)d_in[2];
    const float* Wei  = (const float*)d_in[3];
    const float* Wf1  = (const float*)d_in[4];
    const float* Wf2  = (const float*)d_in[5];
    const float* Wf3  = (const float*)d_in[6];
    const float* We1  = (const float*)d_in[7];
    const float* We2  = (const float*)d_in[8];
    const float* Wn1  = (const float*)d_in[9];
    const float* Wn2  = (const float*)d_in[10];
    const int*   sndr = (const int*)d_in[11];
    const int*   rcvr = (const int*)d_in[12];
    float*       out  = (float*)d_out;

    unsigned* agu = sym_addr<unsigned>(agg_buf);
    float*    u   = sym_addr<float>(u_buf);
    float*    v   = sym_addr<float>(v_buf);
    float*    w   = sym_addr<float>(w_buf);
    unsigned short* GH = sym_addr<unsigned short>(ghi_buf);
    unsigned short* GL = sym_addr<unsigned short>(glo_buf);
    unsigned short* ZH = sym_addr<unsigned short>(zhi_buf);
    unsigned short* ZL = sym_addr<unsigned short>(zlo_buf);
    unsigned short* TH2= sym_addr<unsigned short>(thi_buf);
    unsigned short* TL2= sym_addr<unsigned short>(tlo_buf);
    float*    qh  = sym_addr<float>(qh_buf);
    float*    qt  = sym_addr<float>(qt_buf);
    float*    hl  = sym_addr<float>(hl_buf);
    float*    dh  = sym_addr<float>(dh_buf);
    float*    hA  = sym_addr<float>(hA_buf);
    float*    hB  = sym_addr<float>(hB_buf);
    unsigned* agS = sym_addr<unsigned>(aggS_buf);
    unsigned short* WP = sym_addr<unsigned short>(wpk_buf);

    set_smem((const void*)tcg<1,M_EDGEIN,false,false,false,false,false>);
    set_smem((const void*)tcg<1,M_SUM3  ,false,true ,false,false,true >);
    set_smem((const void*)tcg<2,M_CAT2D ,true ,false,false,false,true >);
    set_smem((const void*)tcg<1,M_SUM3  ,true ,false,true ,true ,false>);
    set_smem((const void*)tcg_jobs);

    const int T = 256;
    const int gN  = (NN + T - 1) / T;
    const int gE  = (EE + T - 1) / T;
    const int gNM = (NN*ML) / T;

    const int TE  = EE / TR;            // 2000
    const int TN  = (NN + TR - 1)/TR;   // 625
    const int THF = (BC*E2C) / TR;      // 1000

    #define CHK(i) (WP + (size_t)(i)*32768)

    auto mkjob = [&](const unsigned short* PH, const unsigned short* PL,
                     const unsigned short* B, float* C,
                     unsigned short* SH, unsigned short* SL,
                     int nb, int M, int flags) -> CJob {
        CJob j; j.PH=PH; j.PL=PL; j.B=B; j.q0=nullptr; j.q1=nullptr; j.Wei=nullptr;
        j.C=C; j.SH=SH; j.SL=SL; j.nblocks=nb; j.M=M; j.flags=flags; return j;
    };
    auto mkedge = [&](const float* q0, const float* q1, const float* W,
                      const unsigned short* B, float* C, int nb) -> CJob {
        CJob j; j.PH=nullptr; j.PL=nullptr; j.B=B; j.q0=q0; j.q1=q1; j.Wei=W;
        j.C=C; j.SH=nullptr; j.SL=nullptr; j.nblocks=nb; j.M=EE; j.flags=4; return j;
    };
    CJob empty = mkjob(nullptr,nullptr,nullptr,nullptr,nullptr,nullptr,0,0,0);

    // ---- visible launches 0..3 (ncu captures visible idx 3 = EDGEIN) ----
    k_prep<<<25, 256>>>(We1, We2, Wn1, Wn2, Wf1, Wf2);          // 0
    k_init<<<gNM, T>>>(x, hA, dh, agS, agu);                    // 1
    k_flows<<<gE, T>>>(hA, r, sndr, rcvr, qh, qt);              // 2
    tcg<1,M_EDGEIN,false,false,false,false,false><<<TE, 128, SM_TOT>>>(   // 3 PROFILED
        qt, Wei, qh, nullptr, nullptr, nullptr, nullptr, nullptr,
        CHK(2), w, nullptr, nullptr, nullptr, nullptr, nullptr, nullptr, EE, 0);
    k_segsum<<<gE, T>>>(qh, rcvr, dh);
    k_node_in<<<gNM, T>>>(dh, x, Wni, GH, GL);

    for (int k = 0; k < K_ITERS; k++){
        if (k > 0){
            k_node_in<<<gNM, T>>>(dh, x, Wni, GH, GL);
            CJobs js = {{ mkedge(qt, qh, Wei, CHK(2), w, TE),
                          mkjob(GH,GL,CHK(0),u,nullptr,nullptr,TN,NN,0),
                          mkjob(GH,GL,CHK(1),v,nullptr,nullptr,TN,NN,0) }};
            tcg_jobs<<<TE+2*TN, 128, SM_TOT>>>(js);
        } else {
            CJobs js = {{ mkjob(GH,GL,CHK(0),u,nullptr,nullptr,TN,NN,0),
                          mkjob(GH,GL,CHK(1),v,nullptr,nullptr,TN,NN,0),
                          empty }};
            tcg_jobs<<<2*TN, 128, SM_TOT>>>(js);
        }

        for (int i = 0; i < I_LAYERS; i++){
            tcg<1,M_SUM3,false,true,false,false,true><<<TE, 128, SM_TOT>>>(
                u, v, w, nullptr, nullptr, nullptr, sndr, rcvr,
                CHK(9+i), nullptr, ZH, ZL, agu, rcvr, nullptr, nullptr, EE, (i==2)?1:0);
            tcg<2,M_CAT2D,true,false,false,false,true><<<TN, 128, SM_TOT>>>(
                nullptr, nullptr, nullptr, agu, GH, GL, nullptr, nullptr,
                CHK(12+2*i), nullptr, TH2, TL2, nullptr, nullptr, nullptr, nullptr, NN, 0);
            if (i < 2){
                CJobs js = {{ mkjob(TH2,TL2,CHK(18+i),nullptr,GH,GL,TN,NN,1),
                              mkjob(ZH,ZL,CHK((i+1)*3+2),w,nullptr,nullptr,TE,EE,0),
                              empty }};
                tcg_jobs<<<TN+TE, 128, SM_TOT>>>(js);
                CJobs js2 = {{ mkjob(GH,GL,CHK((i+1)*3),u,nullptr,nullptr,TN,NN,0),
                               mkjob(GH,GL,CHK((i+1)*3+1),v,nullptr,nullptr,TN,NN,0),
                               empty }};
                tcg_jobs<<<2*TN, 128, SM_TOT>>>(js2);
            } else {
                CJobs js = {{ mkjob(TH2,TL2,CHK(18+i),nullptr,GH,GL,TN,NN,1),
                              empty, empty }};
                tcg_jobs<<<TN, 128, SM_TOT>>>(js);
            }
        }

        // flow head
        {
            CJobs js = {{ mkjob(GH,GL,CHK(21),u,nullptr,nullptr,TN,NN,0),
                          mkjob(GH,GL,CHK(22),v,nullptr,nullptr,TN,NN,0),
                          mkjob(ZH,ZL,CHK(23),w,nullptr,nullptr,THF,EE,2) }};
            tcg_jobs<<<2*TN+THF, 128, SM_TOT>>>(js);
        }
        tcg<1,M_SUM3,true,false,true,true,false><<<THF, 128, SM_TOT>>>(
            u, v, w, nullptr, nullptr, nullptr, sndr, rcvr,
            CHK(24), nullptr, nullptr, nullptr, nullptr, nullptr, Wf3, qh, EE, 0);

        k_misc<<<gE, T>>>(qh, r, x, rcvr, hl, dh, hA);

        float* hc = hA; float* hn = hB;
        for (int j = 0; j < J_HEADS; j++){
            k_head_edge<<<gE, T>>>(hc, hl, sndr, rcvr, agS);
            k_head_node<<<gN, T>>>(agS, hc, x, hn);
            float* t2 = hc; hc = hn; hn = t2;
        }

        k_flows<<<gE, T>>>(hc, r, sndr, rcvr, qt, nullptr);
    }

    k_copy<<<gN, T>>>(hA, out, NN);
    (void)in_sizes; (void)n_in; (void)out_size;
    #undef CHK
}